// round 9
// baseline (speedup 1.0000x reference)
#include <cuda_runtime.h>
#include <math.h>
#include <stdint.h>

#define NB   4
#define LSEQ 4096
#define EMB  1024
#define NH   16
#define HD   64
#define WIN  256
#define OV   32
#define KWIN 320      // WIN + 2*OV
#define NWIN 16       // LSEQ / WIN

// Scratch (device globals -- no allocation allowed)
__device__ float g_q[(size_t)NB * LSEQ * EMB];
__device__ float g_k[(size_t)NB * LSEQ * EMB];
__device__ float g_v[(size_t)NB * LSEQ * EMB];
__device__ float g_att[(size_t)NB * LSEQ * EMB];

// ===========================================================================
// helpers
// ===========================================================================
__device__ __forceinline__ uint32_t smem_u32(const void* p) {
    uint32_t a;
    asm("{ .reg .u64 t; cvta.to.shared.u64 t, %1; cvt.u32.u64 %0, t; }"
        : "=r"(a) : "l"(p));
    return a;
}

__device__ __forceinline__ void cp_async16(uint32_t s, const void* g) {
    asm volatile("cp.async.cg.shared.global [%0], [%1], 16;" :: "r"(s), "l"(g));
}
#define CP_COMMIT() asm volatile("cp.async.commit_group;" ::: "memory")
#define CP_WAIT(N)  asm volatile("cp.async.wait_group %0;" :: "n"(N) : "memory")

// D = A(16x8) * B(8x8) + D, tf32 operands as raw fp32 bits (HW truncates)
#define MMA_TF32(c, a0, a1, a2, a3, b0, b1) \
    asm volatile("mma.sync.aligned.m16n8k8.row.col.f32.tf32.tf32.f32 " \
                 "{%0,%1,%2,%3}, {%4,%5,%6,%7}, {%8,%9}, {%0,%1,%2,%3};" \
                 : "+f"((c)[0]), "+f"((c)[1]), "+f"((c)[2]), "+f"((c)[3]) \
                 : "r"(a0), "r"(a1), "r"(a2), "r"(a3), "r"(b0), "r"(b1))

// ---------------------------------------------------------------------------
// Kernel 1: fused q/k/v per-head projection (R2 scalar version, known 340us).
// out[r, h, e] = sum_d X[r, h, d] * W[e, d]
// grid: (NB*LSEQ/64, NH, 3), block: 256
// ---------------------------------------------------------------------------
__global__ __launch_bounds__(256) void proj_kernel(
    const float* __restrict__ vals, const float* __restrict__ keys,
    const float* __restrict__ qrs,
    const float* __restrict__ Wv, const float* __restrict__ Wk,
    const float* __restrict__ Wq)
{
    __shared__ float sW[64][65];
    __shared__ float sX[64][65];

    const float* X; const float* W; float* O;
    switch (blockIdx.z) {
        case 0:  X = vals; W = Wv; O = g_v; break;
        case 1:  X = keys; W = Wk; O = g_k; break;
        default: X = qrs;  W = Wq; O = g_q; break;
    }
    const int h  = blockIdx.y;
    const size_t r0 = (size_t)blockIdx.x * 64;
    const int t  = threadIdx.x;

    for (int i = t; i < 64 * 64; i += 256) sW[i >> 6][i & 63] = W[i];
    for (int i = t; i < 64 * 64; i += 256) {
        int r = i >> 6, dd = i & 63;
        sX[r][dd] = X[(r0 + r) * EMB + h * HD + dd];
    }
    __syncthreads();

    const int tx = t & 15, ty = t >> 4;
    float acc[4][4] = {};
    #pragma unroll 8
    for (int dd = 0; dd < 64; dd++) {
        float a[4], b[4];
        #pragma unroll
        for (int i = 0; i < 4; i++) a[i] = sX[ty * 4 + i][dd];
        #pragma unroll
        for (int j = 0; j < 4; j++) b[j] = sW[tx * 4 + j][dd];
        #pragma unroll
        for (int i = 0; i < 4; i++)
            #pragma unroll
            for (int j = 0; j < 4; j++) acc[i][j] += a[i] * b[j];
    }

    #pragma unroll
    for (int i = 0; i < 4; i++)
        #pragma unroll
        for (int j = 0; j < 4; j++)
            O[(r0 + ty * 4 + i) * EMB + h * HD + tx * 4 + j] = acc[i][j];
}

// ---------------------------------------------------------------------------
// Kernel 2: overlapping-window attention (scalar fp32, unchanged).
// ---------------------------------------------------------------------------
__global__ __launch_bounds__(256, 1) void attn_kernel(const int* __restrict__ mask)
{
    extern __shared__ float sm[];
    float* sK = sm;
    float* sV = sm + KWIN * HD;

    const int w  = blockIdx.x;
    const int h  = blockIdx.y;
    const int nb = blockIdx.z;
    const int t  = threadIdx.x;
    const size_t qbase = (size_t)nb * LSEQ + (size_t)w * WIN;

    for (int i = t; i < WIN * HD; i += 256) {
        int r = i >> 6, dd = i & 63;
        sK[r * 64 + ((dd + r) & 63)] = g_q[(qbase + r) * EMB + h * HD + dd];
    }
    __syncthreads();
    float q[64];
    #pragma unroll
    for (int i = 0; i < 64; i++) q[i] = sK[t * 64 + ((i + t) & 63)];
    __syncthreads();

    const float4* gk4 = (const float4*)g_k;
    const float4* gv4 = (const float4*)g_v;
    float4* sK4 = (float4*)sK;
    float4* sV4 = (float4*)sV;
    for (int i = t; i < KWIN * (HD / 4); i += 256) {
        int j = i >> 4, u = i & 15;
        int tok = w * WIN + j - OV;
        float4 kk = make_float4(0.f, 0.f, 0.f, 0.f);
        float4 vv = make_float4(0.f, 0.f, 0.f, 0.f);
        if ((unsigned)tok < (unsigned)LSEQ) {
            size_t idx = (((size_t)nb * LSEQ + tok) * EMB + h * HD) / 4 + u;
            kk = gk4[idx];
            vv = gv4[idx];
        }
        sK4[i] = kk;
        sV4[i] = vv;
    }
    __syncthreads();

    const int qtok = w * WIN + t;
    const bool qv  = mask[(size_t)nb * LSEQ + qtok] != 0;

    float m = -INFINITY, l = 0.f;
    float acc[64];
    #pragma unroll
    for (int i = 0; i < 64; i++) acc[i] = 0.f;

    for (int c = 0; c < KWIN / 16; c++) {
        float s[16];
        float cmax = -INFINITY;
        #pragma unroll
        for (int jj = 0; jj < 16; jj++) {
            const int j = c * 16 + jj;
            const float4* kr = (const float4*)(sK + j * 64);
            float s0 = 0.f, s1 = 0.f, s2 = 0.f, s3 = 0.f;
            #pragma unroll
            for (int u = 0; u < 16; u++) {
                float4 k4 = kr[u];
                s0 += q[4 * u + 0] * k4.x;
                s1 += q[4 * u + 1] * k4.y;
                s2 += q[4 * u + 2] * k4.z;
                s3 += q[4 * u + 3] * k4.w;
            }
            float sc = ((s0 + s1) + (s2 + s3)) * 0.125f;
            if (!qv) sc = -1.25e9f;
            int tok = w * WIN + j - OV;
            if ((unsigned)tok >= (unsigned)LSEQ) sc = -INFINITY;
            s[jj] = sc;
            cmax = fmaxf(cmax, sc);
        }
        const float mn = fmaxf(m, cmax);
        if (mn == -INFINITY) continue;
        const float corr = __expf(m - mn);
        l *= corr;
        #pragma unroll
        for (int i = 0; i < 64; i++) acc[i] *= corr;
        #pragma unroll
        for (int jj = 0; jj < 16; jj++) {
            const int j = c * 16 + jj;
            const float p = __expf(s[jj] - mn);
            l += p;
            const float4* vr = (const float4*)(sV + j * 64);
            #pragma unroll
            for (int u = 0; u < 16; u++) {
                float4 v4 = vr[u];
                acc[4 * u + 0] += p * v4.x;
                acc[4 * u + 1] += p * v4.y;
                acc[4 * u + 2] += p * v4.z;
                acc[4 * u + 3] += p * v4.w;
            }
        }
        m = mn;
    }

    const float inv = (l > 0.f) ? (1.f / l) : 0.f;

    __syncthreads();
    #pragma unroll
    for (int i = 0; i < 64; i++) sK[t * 64 + ((i + t) & 63)] = acc[i] * inv;
    __syncthreads();
    for (int i = t; i < WIN * HD; i += 256) {
        int r = i >> 6, dd = i & 63;
        g_att[(qbase + r) * EMB + h * HD + dd] = sK[r * 64 + ((dd + r) & 63)];
    }
}

// ---------------------------------------------------------------------------
// Kernel 3: output projection via mma.sync tf32 (K=1024, no splitting).
// out[16384,1024] = g_att @ Wf^T + bf,  D[m][n] = sum_k A[m][k]*B[n][k]
// Block tile 128x128, BK=32 fp32, 3-stage cp.async pipeline, 8 warps (2Mx4N),
// warp tile 64x32.  smem rows stride 36 floats -> conflict-free frag loads
// (bank = 4*(lane>>2) + (lane&3), all 32 banks distinct).
// grid: (8, 128), block 256, 2 CTAs/SM.
// ---------------------------------------------------------------------------
#define BK        32
#define KTILES    (EMB / BK)            // 32
#define ROW_F     36                    // floats per smem row (144 B)
#define TILE_F    (128 * ROW_F)         // floats per A (or B) tile = 4608
#define STAGE_F   (2 * TILE_F)          // A + B per stage = 9216 floats
#define NSTAGE    3
#define SMEM_GEMM (NSTAGE * STAGE_F * 4)  // 110,592 bytes

__global__ __launch_bounds__(256, 2) void out_gemm_tf32(
    const float* __restrict__ Wf, const float* __restrict__ bf,
    float* __restrict__ out)
{
    extern __shared__ float sg[];
    const uint32_t sb = smem_u32(sg);
    const int tid  = threadIdx.x, lane = tid & 31, wid = tid >> 5;
    const int wm   = (wid & 1) * 64;
    const int wn   = (wid >> 1) * 32;
    const size_t m0 = (size_t)blockIdx.y * 128;
    const int e0   = blockIdx.x * 128;

    const int lr = lane >> 2;       // fragment row within 8
    const int lc = lane & 3;        // fragment k within 4

    // fill mapping: 4 chunks each for A and B per stage
    const int frow = tid >> 3;      // rows covered in 4 steps of 32
    const int fc   = tid & 7;       // 16B chunk within 32-float row

    float c[4][4][4];
    #pragma unroll
    for (int i = 0; i < 4; i++)
        #pragma unroll
        for (int j = 0; j < 4; j++)
            #pragma unroll
            for (int u = 0; u < 4; u++) c[i][j][u] = 0.f;

    // ---- issue one stage's loads ----
    auto issue = [&](int s) {
        const int buf = s % NSTAGE;
        const int k0  = s * BK;
        const uint32_t sa = sb + (uint32_t)(buf * STAGE_F) * 4u;
        const uint32_t sbb = sa + (uint32_t)TILE_F * 4u;
        #pragma unroll
        for (int it = 0; it < 4; it++) {
            const int r = it * 32 + frow;
            cp_async16(sa  + (uint32_t)(r * ROW_F + fc * 4) * 4u,
                       &g_att[(m0 + r) * EMB + k0 + fc * 4]);
            cp_async16(sbb + (uint32_t)(r * ROW_F + fc * 4) * 4u,
                       &Wf[(size_t)(e0 + r) * EMB + k0 + fc * 4]);
        }
        CP_COMMIT();
    };

    issue(0);
    issue(1);

    for (int t = 0; t < KTILES; t++) {
        if (t < KTILES - 1) { CP_WAIT(1); } else { CP_WAIT(0); }
        __syncthreads();

        if (t + 2 < KTILES) issue(t + 2);

        const int buf = t % NSTAGE;
        const float* As = sg + buf * STAGE_F;
        const float* Bs = As + TILE_F;

        #pragma unroll
        for (int ks = 0; ks < 4; ks++) {
            uint32_t a[4][4];
            #pragma unroll
            for (int mt = 0; mt < 4; mt++) {
                const int base = (wm + mt * 16 + lr) * ROW_F + ks * 8 + lc;
                a[mt][0] = __float_as_uint(As[base]);
                a[mt][1] = __float_as_uint(As[base + 8 * ROW_F]);
                a[mt][2] = __float_as_uint(As[base + 4]);
                a[mt][3] = __float_as_uint(As[base + 8 * ROW_F + 4]);
            }
            #pragma unroll
            for (int nf = 0; nf < 4; nf++) {
                const int bbase = (wn + nf * 8 + lr) * ROW_F + ks * 8 + lc;
                const uint32_t b0 = __float_as_uint(Bs[bbase]);
                const uint32_t b1 = __float_as_uint(Bs[bbase + 4]);
                #pragma unroll
                for (int mt = 0; mt < 4; mt++)
                    MMA_TF32(c[mt][nf], a[mt][0], a[mt][1], a[mt][2], a[mt][3],
                             b0, b1);
            }
        }
        __syncthreads();
    }

    // ---- epilogue: bias + direct stores ----
    #pragma unroll
    for (int mt = 0; mt < 4; mt++) {
        #pragma unroll
        for (int nf = 0; nf < 4; nf++) {
            const int m   = (int)m0 + wm + mt * 16 + lr;
            const int col = e0 + wn + nf * 8 + lc * 2;
            const float b0 = bf[col], b1 = bf[col + 1];
            float2 v0 = make_float2(c[mt][nf][0] + b0, c[mt][nf][1] + b1);
            float2 v1 = make_float2(c[mt][nf][2] + b0, c[mt][nf][3] + b1);
            *(float2*)&out[(size_t)m * EMB + col] = v0;
            *(float2*)&out[(size_t)(m + 8) * EMB + col] = v1;
        }
    }
}

// ---------------------------------------------------------------------------
extern "C" void kernel_launch(void* const* d_in, const int* in_sizes, int n_in,
                              void* d_out, int out_size)
{
    const float* vals = (const float*)d_in[0];
    const float* keys = (const float*)d_in[1];
    const float* qrs  = (const float*)d_in[2];
    const int*   mask = (const int*)d_in[3];
    const float* Wv   = (const float*)d_in[4];
    const float* Wk   = (const float*)d_in[5];
    const float* Wq   = (const float*)d_in[6];
    const float* Wf   = (const float*)d_in[7];
    const float* bf   = (const float*)d_in[8];
    float* out = (float*)d_out;

    const int attn_smem = 2 * KWIN * HD * (int)sizeof(float);  // 160 KB
    cudaFuncSetAttribute(attn_kernel,
                         cudaFuncAttributeMaxDynamicSharedMemorySize, attn_smem);
    cudaFuncSetAttribute(out_gemm_tf32,
                         cudaFuncAttributeMaxDynamicSharedMemorySize, SMEM_GEMM);

    proj_kernel<<<dim3(NB * LSEQ / 64, NH, 3), 256>>>(vals, keys, qrs, Wv, Wk, Wq);
    attn_kernel<<<dim3(NWIN, NH, NB), 256, attn_smem>>>(mask);
    out_gemm_tf32<<<dim3(EMB / 128, NB * LSEQ / 128), 256, SMEM_GEMM>>>(Wf, bf, out);
}

// round 10
// speedup vs baseline: 1.0332x; 1.0332x over previous
#include <cuda_runtime.h>
#include <math.h>
#include <stdint.h>

#define NB   4
#define LSEQ 4096
#define EMB  1024
#define NH   16
#define HD   64
#define WIN  256
#define OV   32
#define KWIN 320
#define NWIN 16

__device__ float g_q[(size_t)NB * LSEQ * EMB];
__device__ float g_k[(size_t)NB * LSEQ * EMB];
__device__ float g_v[(size_t)NB * LSEQ * EMB];
__device__ float g_att[(size_t)NB * LSEQ * EMB];

// ===========================================================================
__device__ __forceinline__ uint32_t smem_u32(const void* p) {
    uint32_t a;
    asm("{ .reg .u64 t; cvta.to.shared.u64 t, %1; cvt.u32.u64 %0, t; }"
        : "=r"(a) : "l"(p));
    return a;
}
__device__ __forceinline__ void cp_async16(uint32_t s, const void* g) {
    asm volatile("cp.async.cg.shared.global [%0], [%1], 16;" :: "r"(s), "l"(g));
}
#define CP_COMMIT() asm volatile("cp.async.commit_group;" ::: "memory")
#define CP_WAIT(N)  asm volatile("cp.async.wait_group %0;" :: "n"(N) : "memory")

__device__ __forceinline__ uint32_t bf16_rn_bits(float x) {
    uint32_t xi = __float_as_uint(x);
    return (xi + 0x7FFFu + ((xi >> 16) & 1u)) >> 16;
}
// pack two k-consecutive values: returns {hi|hi, lo|lo} words (bf16x2)
__device__ __forceinline__ uint2 splitW(float x, float y) {
    uint32_t xi = __float_as_uint(x), yi = __float_as_uint(y);
    float rx = x - __uint_as_float(xi & 0xFFFF0000u);
    float ry = y - __uint_as_float(yi & 0xFFFF0000u);
    return make_uint2((xi >> 16) | ((yi >> 16) << 16),
                      bf16_rn_bits(rx) | (bf16_rn_bits(ry) << 16));
}
// RNA tf32 (bits in fp32 register format)
__device__ __forceinline__ uint32_t f2tf(float x) {
    uint32_t r;
    asm("cvt.rna.tf32.f32 %0, %1;" : "=r"(r) : "f"(x));
    return r;
}

#define MMA_TF32(c, a0, a1, a2, a3, b0, b1) \
    asm volatile("mma.sync.aligned.m16n8k8.row.col.f32.tf32.tf32.f32 " \
                 "{%0,%1,%2,%3}, {%4,%5,%6,%7}, {%8,%9}, {%0,%1,%2,%3};" \
                 : "+f"((c)[0]), "+f"((c)[1]), "+f"((c)[2]), "+f"((c)[3]) \
                 : "r"(a0), "r"(a1), "r"(a2), "r"(a3), "r"(b0), "r"(b1))

#define MMA_BF16(c, a0, a1, a2, a3, b0, b1) \
    asm volatile("mma.sync.aligned.m16n8k16.row.col.f32.bf16.bf16.f32 " \
                 "{%0,%1,%2,%3}, {%4,%5,%6,%7}, {%8,%9}, {%0,%1,%2,%3};" \
                 : "+f"((c)[0]), "+f"((c)[1]), "+f"((c)[2]), "+f"((c)[3]) \
                 : "r"(a0), "r"(a1), "r"(a2), "r"(a3), "r"(b0), "r"(b1))

// ---------------------------------------------------------------------------
// Kernel 1: q/k/v per-head projection (scalar fp32, known-good 340us).
// ---------------------------------------------------------------------------
__global__ __launch_bounds__(256) void proj_kernel(
    const float* __restrict__ vals, const float* __restrict__ keys,
    const float* __restrict__ qrs,
    const float* __restrict__ Wv, const float* __restrict__ Wk,
    const float* __restrict__ Wq)
{
    __shared__ float sW[64][65];
    __shared__ float sX[64][65];

    const float* X; const float* W; float* O;
    switch (blockIdx.z) {
        case 0:  X = vals; W = Wv; O = g_v; break;
        case 1:  X = keys; W = Wk; O = g_k; break;
        default: X = qrs;  W = Wq; O = g_q; break;
    }
    const int h  = blockIdx.y;
    const size_t r0 = (size_t)blockIdx.x * 64;
    const int t  = threadIdx.x;

    for (int i = t; i < 64 * 64; i += 256) sW[i >> 6][i & 63] = W[i];
    for (int i = t; i < 64 * 64; i += 256) {
        int r = i >> 6, dd = i & 63;
        sX[r][dd] = X[(r0 + r) * EMB + h * HD + dd];
    }
    __syncthreads();

    const int tx = t & 15, ty = t >> 4;
    float acc[4][4] = {};
    #pragma unroll 8
    for (int dd = 0; dd < 64; dd++) {
        float a[4], b[4];
        #pragma unroll
        for (int i = 0; i < 4; i++) a[i] = sX[ty * 4 + i][dd];
        #pragma unroll
        for (int j = 0; j < 4; j++) b[j] = sW[tx * 4 + j][dd];
        #pragma unroll
        for (int i = 0; i < 4; i++)
            #pragma unroll
            for (int j = 0; j < 4; j++) acc[i][j] += a[i] * b[j];
    }
    #pragma unroll
    for (int i = 0; i < 4; i++)
        #pragma unroll
        for (int j = 0; j < 4; j++)
            O[(r0 + ty * 4 + i) * EMB + h * HD + tx * 4 + j] = acc[i][j];
}

// ---------------------------------------------------------------------------
// Kernel 2: attention via mma.sync bf16, 3-pass hi/lo split.
// Block = (window, head, batch), 256 threads (8 warps x 32 query rows).
// 5 chunks of 64 tokens; per-thread row softmax; O in mma C-fragments.
// Word tiles (bf16x2 along k) stride 36 words; S/P rows stride 68 floats.
// Fragment LDS bank = (4*row + word) % 32 -> conflict-free.
// ---------------------------------------------------------------------------
#define AQW 36
#define ASW 68
#define O_QH 0
#define O_QL (O_QH + 256 * AQW)
#define O_KH (O_QL + 256 * AQW)
#define O_KL (O_KH + 64 * AQW)
#define O_VH (O_KL + 64 * AQW)
#define O_VL (O_VH + 64 * AQW)
#define O_S  (O_VL + 64 * AQW)
#define O_CR (O_S + 256 * ASW)
#define ATT_SMEM ((O_CR + 256) * 4)       // 181,248 B

__global__ __launch_bounds__(256, 1) void attn_mma(const int* __restrict__ mask)
{
    extern __shared__ uint32_t sw[];
    float* sf = (float*)sw;

    const int w = blockIdx.x, h = blockIdx.y, nb = blockIdx.z;
    const int t = threadIdx.x, lane = t & 31, wid = t >> 5;
    const int lr = lane >> 2, lc = lane & 3;
    const int wm = wid * 32;
    const size_t qbase = (size_t)nb * LSEQ + (size_t)w * WIN;

    // ---- Q load + split (one-time) ----
    for (int i = t; i < 256 * 16; i += 256) {
        int r = i >> 4, g = i & 15;
        float4 v = *(const float4*)&g_q[(qbase + r) * EMB + h * HD + g * 4];
        uint2 w01 = splitW(v.x, v.y), w23 = splitW(v.z, v.w);
        sw[O_QH + r * AQW + g * 2]     = w01.x;
        sw[O_QH + r * AQW + g * 2 + 1] = w23.x;
        sw[O_QL + r * AQW + g * 2]     = w01.y;
        sw[O_QL + r * AQW + g * 2 + 1] = w23.y;
    }
    const bool qv = mask[qbase + t] != 0;

    float m = -INFINITY, l = 0.f;
    float cO[2][8][4];
    #pragma unroll
    for (int mt = 0; mt < 2; mt++)
        #pragma unroll
        for (int nf = 0; nf < 8; nf++)
            #pragma unroll
            for (int u = 0; u < 4; u++) cO[mt][nf][u] = 0.f;

    for (int c = 0; c < 5; c++) {
        __syncthreads();   // prev-iter smem reads done before overwrite

        // ---- K chunk [64 tok][64 d] split, natural layout ----
        for (int i = t; i < 64 * 16; i += 256) {
            int r = i >> 4, g = i & 15;
            int tok = w * WIN + c * 64 + r - OV;
            float4 v = make_float4(0.f, 0.f, 0.f, 0.f);
            if ((unsigned)tok < (unsigned)LSEQ)
                v = *(const float4*)&g_k[((size_t)nb * LSEQ + tok) * EMB + h * HD + g * 4];
            uint2 w01 = splitW(v.x, v.y), w23 = splitW(v.z, v.w);
            sw[O_KH + r * AQW + g * 2]     = w01.x;
            sw[O_KH + r * AQW + g * 2 + 1] = w23.x;
            sw[O_KL + r * AQW + g * 2]     = w01.y;
            sw[O_KL + r * AQW + g * 2 + 1] = w23.y;
        }
        // ---- V chunk transposed: [dim][token-pair words] ----
        for (int i = t; i < 512; i += 256) {
            int tp = i & 31, g = i >> 5;           // token pair, dim group
            int tok0 = w * WIN + c * 64 + 2 * tp - OV;
            float4 a = make_float4(0.f, 0.f, 0.f, 0.f), b = a;
            if ((unsigned)tok0 < (unsigned)LSEQ)
                a = *(const float4*)&g_v[((size_t)nb * LSEQ + tok0) * EMB + h * HD + g * 4];
            if ((unsigned)(tok0 + 1) < (unsigned)LSEQ)
                b = *(const float4*)&g_v[((size_t)nb * LSEQ + tok0 + 1) * EMB + h * HD + g * 4];
            const float ax[4] = {a.x, a.y, a.z, a.w};
            const float bx[4] = {b.x, b.y, b.z, b.w};
            #pragma unroll
            for (int di = 0; di < 4; di++) {
                uint2 ww = splitW(ax[di], bx[di]);
                sw[O_VH + (g * 4 + di) * AQW + tp] = ww.x;
                sw[O_VL + (g * 4 + di) * AQW + tp] = ww.y;
            }
        }
        __syncthreads();

        // ---- S = Q K^T (3 passes) ----
        float cS[2][8][4];
        #pragma unroll
        for (int mt = 0; mt < 2; mt++)
            #pragma unroll
            for (int nf = 0; nf < 8; nf++)
                #pragma unroll
                for (int u = 0; u < 4; u++) cS[mt][nf][u] = 0.f;

        #pragma unroll
        for (int pass = 0; pass < 3; pass++) {
            const int ab = (pass == 1) ? O_QL : O_QH;
            const int bb = (pass == 2) ? O_KL : O_KH;
            #pragma unroll
            for (int ks = 0; ks < 4; ks++) {
                uint32_t a[2][4];
                #pragma unroll
                for (int mt = 0; mt < 2; mt++) {
                    int base = ab + (wm + mt * 16 + lr) * AQW + ks * 8 + lc;
                    a[mt][0] = sw[base];
                    a[mt][1] = sw[base + 8 * AQW];
                    a[mt][2] = sw[base + 4];
                    a[mt][3] = sw[base + 8 * AQW + 4];
                }
                #pragma unroll
                for (int nf = 0; nf < 8; nf++) {
                    int bbase = bb + (nf * 8 + lr) * AQW + ks * 8 + lc;
                    uint32_t b0 = sw[bbase], b1 = sw[bbase + 4];
                    MMA_BF16(cS[0][nf], a[0][0], a[0][1], a[0][2], a[0][3], b0, b1);
                    MMA_BF16(cS[1][nf], a[1][0], a[1][1], a[1][2], a[1][3], b0, b1);
                }
            }
        }
        // store S fragments
        #pragma unroll
        for (int mt = 0; mt < 2; mt++) {
            int row = wm + mt * 16 + lr;
            #pragma unroll
            for (int nf = 0; nf < 8; nf++) {
                int tc = nf * 8 + lc * 2;
                *(float2*)(sf + O_S + row * ASW + tc) =
                    make_float2(cS[mt][nf][0], cS[mt][nf][1]);
                *(float2*)(sf + O_S + (row + 8) * ASW + tc) =
                    make_float2(cS[mt][nf][2], cS[mt][nf][3]);
            }
        }
        __syncthreads();

        // ---- per-thread row softmax (thread t owns query row t) ----
        float p[64];
        float cmax = -INFINITY;
        #pragma unroll
        for (int j = 0; j < 64; j++) {
            float s = sf[O_S + t * ASW + j] * 0.125f;
            int tok = w * WIN + c * 64 + j - OV;
            if (!qv) s = -1.25e9f;
            if ((unsigned)tok >= (unsigned)LSEQ) s = -INFINITY;
            p[j] = s;
            cmax = fmaxf(cmax, s);
        }
        const float mn = fmaxf(m, cmax);           // finite (every chunk has valid keys)
        const float corr = __expf(m - mn);
        l *= corr;
        float ls = 0.f;
        #pragma unroll
        for (int j = 0; j < 64; j++) { p[j] = __expf(p[j] - mn); ls += p[j]; }
        l += ls;
        m = mn;
        sf[O_CR + t] = corr;
        // pack P (hi words 0..31, lo words 32..63) into the S region
        #pragma unroll
        for (int j = 0; j < 32; j++) {
            uint2 ww = splitW(p[2 * j], p[2 * j + 1]);
            sw[O_S + t * ASW + j]      = ww.x;
            sw[O_S + t * ASW + 32 + j] = ww.y;
        }
        __syncthreads();

        // ---- rescale O fragments by per-row corr ----
        #pragma unroll
        for (int mt = 0; mt < 2; mt++) {
            float c0 = sf[O_CR + wm + mt * 16 + lr];
            float c1 = sf[O_CR + wm + mt * 16 + lr + 8];
            #pragma unroll
            for (int nf = 0; nf < 8; nf++) {
                cO[mt][nf][0] *= c0; cO[mt][nf][1] *= c0;
                cO[mt][nf][2] *= c1; cO[mt][nf][3] *= c1;
            }
        }
        // ---- O += P V (3 passes) ----
        #pragma unroll
        for (int pass = 0; pass < 3; pass++) {
            const int ab = O_S + ((pass == 1) ? 32 : 0);
            const int bb = (pass == 2) ? O_VL : O_VH;
            #pragma unroll
            for (int ks = 0; ks < 4; ks++) {
                uint32_t a[2][4];
                #pragma unroll
                for (int mt = 0; mt < 2; mt++) {
                    int base = ab + (wm + mt * 16 + lr) * ASW + ks * 8 + lc;
                    a[mt][0] = sw[base];
                    a[mt][1] = sw[base + 8 * ASW];
                    a[mt][2] = sw[base + 4];
                    a[mt][3] = sw[base + 8 * ASW + 4];
                }
                #pragma unroll
                for (int nf = 0; nf < 8; nf++) {
                    int bbase = bb + (nf * 8 + lr) * AQW + ks * 8 + lc;
                    uint32_t b0 = sw[bbase], b1 = sw[bbase + 4];
                    MMA_BF16(cO[0][nf], a[0][0], a[0][1], a[0][2], a[0][3], b0, b1);
                    MMA_BF16(cO[1][nf], a[1][0], a[1][1], a[1][2], a[1][3], b0, b1);
                }
            }
        }
    }

    // ---- finalize: 1/l scaling, store ----
    const float inv = (l > 0.f) ? (1.f / l) : 0.f;
    __syncthreads();
    sf[O_CR + t] = inv;
    __syncthreads();
    #pragma unroll
    for (int mt = 0; mt < 2; mt++) {
        const int r = wm + mt * 16 + lr;
        const float i0 = sf[O_CR + r], i1 = sf[O_CR + r + 8];
        #pragma unroll
        for (int nf = 0; nf < 8; nf++) {
            int col = h * HD + nf * 8 + lc * 2;
            *(float2*)&g_att[(qbase + r) * EMB + col] =
                make_float2(cO[mt][nf][0] * i0, cO[mt][nf][1] * i0);
            *(float2*)&g_att[(qbase + r + 8) * EMB + col] =
                make_float2(cO[mt][nf][2] * i1, cO[mt][nf][3] * i1);
        }
    }
}

// ---------------------------------------------------------------------------
// Kernel 3: output projection, 3xTF32 mma (RNA hi/lo split), cp.async x3.
// ---------------------------------------------------------------------------
#define BK        32
#define KTILES    (EMB / BK)
#define ROW_F     36
#define TILE_F    (128 * ROW_F)
#define STAGE_F   (2 * TILE_F)
#define NSTAGE    3
#define SMEM_GEMM (NSTAGE * STAGE_F * 4)

__global__ __launch_bounds__(256, 2) void out_gemm_tf32(
    const float* __restrict__ Wf, const float* __restrict__ bf,
    float* __restrict__ out)
{
    extern __shared__ float sg[];
    const uint32_t sb = smem_u32(sg);
    const int tid  = threadIdx.x, lane = tid & 31, wid = tid >> 5;
    const int wm   = (wid & 1) * 64;
    const int wn   = (wid >> 1) * 32;
    const size_t m0 = (size_t)blockIdx.y * 128;
    const int e0   = blockIdx.x * 128;
    const int lr = lane >> 2, lc = lane & 3;
    const int frow = tid >> 3, fc = tid & 7;

    float c[4][4][4];
    #pragma unroll
    for (int i = 0; i < 4; i++)
        #pragma unroll
        for (int j = 0; j < 4; j++)
            #pragma unroll
            for (int u = 0; u < 4; u++) c[i][j][u] = 0.f;

    auto issue = [&](int s) {
        const int buf = s % NSTAGE;
        const int k0  = s * BK;
        const uint32_t sa = sb + (uint32_t)(buf * STAGE_F) * 4u;
        const uint32_t sbb = sa + (uint32_t)TILE_F * 4u;
        #pragma unroll
        for (int it = 0; it < 4; it++) {
            const int r = it * 32 + frow;
            cp_async16(sa  + (uint32_t)(r * ROW_F + fc * 4) * 4u,
                       &g_att[(m0 + r) * EMB + k0 + fc * 4]);
            cp_async16(sbb + (uint32_t)(r * ROW_F + fc * 4) * 4u,
                       &Wf[(size_t)(e0 + r) * EMB + k0 + fc * 4]);
        }
        CP_COMMIT();
    };

    issue(0);
    issue(1);

    for (int t = 0; t < KTILES; t++) {
        if (t < KTILES - 1) { CP_WAIT(1); } else { CP_WAIT(0); }
        __syncthreads();
        if (t + 2 < KTILES) issue(t + 2);

        const int buf = t % NSTAGE;
        const float* As = sg + buf * STAGE_F;
        const float* Bs = As + TILE_F;

        #pragma unroll
        for (int ks = 0; ks < 4; ks++) {
            uint32_t ah[4][4], al[4][4];
            #pragma unroll
            for (int mt = 0; mt < 4; mt++) {
                const int base = (wm + mt * 16 + lr) * ROW_F + ks * 8 + lc;
                const float v0 = As[base], v1 = As[base + 8 * ROW_F];
                const float v2 = As[base + 4], v3 = As[base + 8 * ROW_F + 4];
                ah[mt][0] = f2tf(v0); al[mt][0] = f2tf(v0 - __uint_as_float(ah[mt][0]));
                ah[mt][1] = f2tf(v1); al[mt][1] = f2tf(v1 - __uint_as_float(ah[mt][1]));
                ah[mt][2] = f2tf(v2); al[mt][2] = f2tf(v2 - __uint_as_float(ah[mt][2]));
                ah[mt][3] = f2tf(v3); al[mt][3] = f2tf(v3 - __uint_as_float(ah[mt][3]));
            }
            #pragma unroll
            for (int nf = 0; nf < 4; nf++) {
                const int bbase = (wn + nf * 8 + lr) * ROW_F + ks * 8 + lc;
                const float w0 = Bs[bbase], w1 = Bs[bbase + 4];
                const uint32_t bh0 = f2tf(w0), bh1 = f2tf(w1);
                const uint32_t bl0 = f2tf(w0 - __uint_as_float(bh0));
                const uint32_t bl1 = f2tf(w1 - __uint_as_float(bh1));
                #pragma unroll
                for (int mt = 0; mt < 4; mt++) {
                    MMA_TF32(c[mt][nf], ah[mt][0], ah[mt][1], ah[mt][2], ah[mt][3], bh0, bh1);
                    MMA_TF32(c[mt][nf], al[mt][0], al[mt][1], al[mt][2], al[mt][3], bh0, bh1);
                    MMA_TF32(c[mt][nf], ah[mt][0], ah[mt][1], ah[mt][2], ah[mt][3], bl0, bl1);
                }
            }
        }
        __syncthreads();
    }

    #pragma unroll
    for (int mt = 0; mt < 4; mt++) {
        #pragma unroll
        for (int nf = 0; nf < 4; nf++) {
            const int mr  = (int)m0 + wm + mt * 16 + lr;
            const int col = e0 + wn + nf * 8 + lc * 2;
            const float b0 = bf[col], b1 = bf[col + 1];
            *(float2*)&out[(size_t)mr * EMB + col] =
                make_float2(c[mt][nf][0] + b0, c[mt][nf][1] + b1);
            *(float2*)&out[(size_t)(mr + 8) * EMB + col] =
                make_float2(c[mt][nf][2] + b0, c[mt][nf][3] + b1);
        }
    }
}

// ---------------------------------------------------------------------------
extern "C" void kernel_launch(void* const* d_in, const int* in_sizes, int n_in,
                              void* d_out, int out_size)
{
    const float* vals = (const float*)d_in[0];
    const float* keys = (const float*)d_in[1];
    const float* qrs  = (const float*)d_in[2];
    const int*   mask = (const int*)d_in[3];
    const float* Wv   = (const float*)d_in[4];
    const float* Wk   = (const float*)d_in[5];
    const float* Wq   = (const float*)d_in[6];
    const float* Wf   = (const float*)d_in[7];
    const float* bf   = (const float*)d_in[8];
    float* out = (float*)d_out;

    cudaFuncSetAttribute(attn_mma,
                         cudaFuncAttributeMaxDynamicSharedMemorySize, ATT_SMEM);
    cudaFuncSetAttribute(out_gemm_tf32,
                         cudaFuncAttributeMaxDynamicSharedMemorySize, SMEM_GEMM);

    proj_kernel<<<dim3(NB * LSEQ / 64, NH, 3), 256>>>(vals, keys, qrs, Wv, Wk, Wq);
    attn_mma<<<dim3(NWIN, NH, NB), 256, ATT_SMEM>>>(mask);
    out_gemm_tf32<<<dim3(EMB / 128, NB * LSEQ / 128), 256, SMEM_GEMM>>>(Wf, bf, out);
}

// round 13
// speedup vs baseline: 1.3271x; 1.2845x over previous
#include <cuda_runtime.h>
#include <math.h>
#include <stdint.h>

#define NB   4
#define LSEQ 4096
#define EMB  1024
#define NH   16
#define HD   64
#define WIN  256
#define OV   32
#define KWIN 320
#define NWIN 16

__device__ float g_q[(size_t)NB * LSEQ * EMB];
__device__ float g_k[(size_t)NB * LSEQ * EMB];
__device__ float g_v[(size_t)NB * LSEQ * EMB];
// attention output, split into packed bf16 hi/lo planes (2 bf16 per word)
__device__ uint32_t g_ahp[(size_t)NB * LSEQ * EMB / 2];
__device__ uint32_t g_alp[(size_t)NB * LSEQ * EMB / 2];
// Wf split planes
__device__ uint32_t g_wfh[(size_t)EMB * EMB / 2];
__device__ uint32_t g_wfl[(size_t)EMB * EMB / 2];

// ===========================================================================
__device__ __forceinline__ uint32_t smem_u32(const void* p) {
    uint32_t a;
    asm("{ .reg .u64 t; cvta.to.shared.u64 t, %1; cvt.u32.u64 %0, t; }"
        : "=r"(a) : "l"(p));
    return a;
}
__device__ __forceinline__ void cp_async16(uint32_t s, const void* g) {
    asm volatile("cp.async.cg.shared.global [%0], [%1], 16;" :: "r"(s), "l"(g));
}
#define CP_COMMIT() asm volatile("cp.async.commit_group;" ::: "memory")
#define CP_WAIT(N)  asm volatile("cp.async.wait_group %0;" :: "n"(N) : "memory")

__device__ __forceinline__ uint32_t bf16_rn_bits(float x) {
    uint32_t xi = __float_as_uint(x);
    return (xi + 0x7FFFu + ((xi >> 16) & 1u)) >> 16;
}
// split two k-consecutive floats -> {hi|hi, lo|lo} packed bf16x2 words
__device__ __forceinline__ uint2 splitW(float x, float y) {
    uint32_t xi = __float_as_uint(x), yi = __float_as_uint(y);
    float rx = x - __uint_as_float(xi & 0xFFFF0000u);
    float ry = y - __uint_as_float(yi & 0xFFFF0000u);
    return make_uint2((xi >> 16) | ((yi >> 16) << 16),
                      bf16_rn_bits(rx) | (bf16_rn_bits(ry) << 16));
}

#define MMA_BF16(c, a0, a1, a2, a3, b0, b1) \
    asm volatile("mma.sync.aligned.m16n8k16.row.col.f32.bf16.bf16.f32 " \
                 "{%0,%1,%2,%3}, {%4,%5,%6,%7}, {%8,%9}, {%0,%1,%2,%3};" \
                 : "+f"((c)[0]), "+f"((c)[1]), "+f"((c)[2]), "+f"((c)[3]) \
                 : "r"(a0), "r"(a1), "r"(a2), "r"(a3), "r"(b0), "r"(b1))

// ---------------------------------------------------------------------------
// Kernel 1: q/k/v per-head projection (scalar fp32, known-good ~338us).
// ---------------------------------------------------------------------------
__global__ __launch_bounds__(256) void proj_kernel(
    const float* __restrict__ vals, const float* __restrict__ keys,
    const float* __restrict__ qrs,
    const float* __restrict__ Wv, const float* __restrict__ Wk,
    const float* __restrict__ Wq)
{
    __shared__ float sW[64][65];
    __shared__ float sX[64][65];

    const float* X; const float* W; float* O;
    switch (blockIdx.z) {
        case 0:  X = vals; W = Wv; O = g_v; break;
        case 1:  X = keys; W = Wk; O = g_k; break;
        default: X = qrs;  W = Wq; O = g_q; break;
    }
    const int h  = blockIdx.y;
    const size_t r0 = (size_t)blockIdx.x * 64;
    const int t  = threadIdx.x;

    for (int i = t; i < 64 * 64; i += 256) sW[i >> 6][i & 63] = W[i];
    for (int i = t; i < 64 * 64; i += 256) {
        int r = i >> 6, dd = i & 63;
        sX[r][dd] = X[(r0 + r) * EMB + h * HD + dd];
    }
    __syncthreads();

    const int tx = t & 15, ty = t >> 4;
    float acc[4][4] = {};
    #pragma unroll 8
    for (int dd = 0; dd < 64; dd++) {
        float a[4], b[4];
        #pragma unroll
        for (int i = 0; i < 4; i++) a[i] = sX[ty * 4 + i][dd];
        #pragma unroll
        for (int j = 0; j < 4; j++) b[j] = sW[tx * 4 + j][dd];
        #pragma unroll
        for (int i = 0; i < 4; i++)
            #pragma unroll
            for (int j = 0; j < 4; j++) acc[i][j] += a[i] * b[j];
    }
    #pragma unroll
    for (int i = 0; i < 4; i++)
        #pragma unroll
        for (int j = 0; j < 4; j++)
            O[(r0 + ty * 4 + i) * EMB + h * HD + tx * 4 + j] = acc[i][j];
}

// ---------------------------------------------------------------------------
// Kernel 1b: split Wf into bf16 hi/lo planes (one-time, tiny).
// ---------------------------------------------------------------------------
__global__ __launch_bounds__(256) void wf_split_kernel(const float* __restrict__ Wf)
{
    const int i = blockIdx.x * 256 + threadIdx.x;      // pair index
    float2 v = *(const float2*)&Wf[2 * i];
    uint2 s = splitW(v.x, v.y);
    g_wfh[i] = s.x;
    g_wfl[i] = s.y;
}

// ---------------------------------------------------------------------------
// Kernel 2: attention via mma.sync bf16, 3-pass hi/lo split.
// Epilogue stores result as packed bf16 hi/lo planes for the final GEMM.
// ---------------------------------------------------------------------------
#define AQW 36
#define ASW 68
#define O_QH 0
#define O_QL (O_QH + 256 * AQW)
#define O_KH (O_QL + 256 * AQW)
#define O_KL (O_KH + 64 * AQW)
#define O_VH (O_KL + 64 * AQW)
#define O_VL (O_VH + 64 * AQW)
#define O_S  (O_VL + 64 * AQW)
#define O_CR (O_S + 256 * ASW)
#define ATT_SMEM ((O_CR + 256) * 4)

__global__ __launch_bounds__(256, 1) void attn_mma(const int* __restrict__ mask)
{
    extern __shared__ uint32_t sw[];
    float* sf = (float*)sw;

    const int w = blockIdx.x, h = blockIdx.y, nb = blockIdx.z;
    const int t = threadIdx.x, lane = t & 31, wid = t >> 5;
    const int lr = lane >> 2, lc = lane & 3;
    const int wm = wid * 32;
    const size_t qbase = (size_t)nb * LSEQ + (size_t)w * WIN;

    for (int i = t; i < 256 * 16; i += 256) {
        int r = i >> 4, g = i & 15;
        float4 v = *(const float4*)&g_q[(qbase + r) * EMB + h * HD + g * 4];
        uint2 w01 = splitW(v.x, v.y), w23 = splitW(v.z, v.w);
        sw[O_QH + r * AQW + g * 2]     = w01.x;
        sw[O_QH + r * AQW + g * 2 + 1] = w23.x;
        sw[O_QL + r * AQW + g * 2]     = w01.y;
        sw[O_QL + r * AQW + g * 2 + 1] = w23.y;
    }
    const bool qv = mask[qbase + t] != 0;

    float m = -INFINITY, l = 0.f;
    float cO[2][8][4];
    #pragma unroll
    for (int mt = 0; mt < 2; mt++)
        #pragma unroll
        for (int nf = 0; nf < 8; nf++)
            #pragma unroll
            for (int u = 0; u < 4; u++) cO[mt][nf][u] = 0.f;

    for (int c = 0; c < 5; c++) {
        __syncthreads();

        for (int i = t; i < 64 * 16; i += 256) {
            int r = i >> 4, g = i & 15;
            int tok = w * WIN + c * 64 + r - OV;
            float4 v = make_float4(0.f, 0.f, 0.f, 0.f);
            if ((unsigned)tok < (unsigned)LSEQ)
                v = *(const float4*)&g_k[((size_t)nb * LSEQ + tok) * EMB + h * HD + g * 4];
            uint2 w01 = splitW(v.x, v.y), w23 = splitW(v.z, v.w);
            sw[O_KH + r * AQW + g * 2]     = w01.x;
            sw[O_KH + r * AQW + g * 2 + 1] = w23.x;
            sw[O_KL + r * AQW + g * 2]     = w01.y;
            sw[O_KL + r * AQW + g * 2 + 1] = w23.y;
        }
        for (int i = t; i < 512; i += 256) {
            int tp = i & 31, g = i >> 5;
            int tok0 = w * WIN + c * 64 + 2 * tp - OV;
            float4 a = make_float4(0.f, 0.f, 0.f, 0.f), b = a;
            if ((unsigned)tok0 < (unsigned)LSEQ)
                a = *(const float4*)&g_v[((size_t)nb * LSEQ + tok0) * EMB + h * HD + g * 4];
            if ((unsigned)(tok0 + 1) < (unsigned)LSEQ)
                b = *(const float4*)&g_v[((size_t)nb * LSEQ + tok0 + 1) * EMB + h * HD + g * 4];
            const float ax[4] = {a.x, a.y, a.z, a.w};
            const float bx[4] = {b.x, b.y, b.z, b.w};
            #pragma unroll
            for (int di = 0; di < 4; di++) {
                uint2 ww = splitW(ax[di], bx[di]);
                sw[O_VH + (g * 4 + di) * AQW + tp] = ww.x;
                sw[O_VL + (g * 4 + di) * AQW + tp] = ww.y;
            }
        }
        __syncthreads();

        float cS[2][8][4];
        #pragma unroll
        for (int mt = 0; mt < 2; mt++)
            #pragma unroll
            for (int nf = 0; nf < 8; nf++)
                #pragma unroll
                for (int u = 0; u < 4; u++) cS[mt][nf][u] = 0.f;

        #pragma unroll
        for (int pass = 0; pass < 3; pass++) {
            const int ab = (pass == 1) ? O_QL : O_QH;
            const int bb = (pass == 2) ? O_KL : O_KH;
            #pragma unroll
            for (int ks = 0; ks < 4; ks++) {
                uint32_t a[2][4];
                #pragma unroll
                for (int mt = 0; mt < 2; mt++) {
                    int base = ab + (wm + mt * 16 + lr) * AQW + ks * 8 + lc;
                    a[mt][0] = sw[base];
                    a[mt][1] = sw[base + 8 * AQW];
                    a[mt][2] = sw[base + 4];
                    a[mt][3] = sw[base + 8 * AQW + 4];
                }
                #pragma unroll
                for (int nf = 0; nf < 8; nf++) {
                    int bbase = bb + (nf * 8 + lr) * AQW + ks * 8 + lc;
                    uint32_t b0 = sw[bbase], b1 = sw[bbase + 4];
                    MMA_BF16(cS[0][nf], a[0][0], a[0][1], a[0][2], a[0][3], b0, b1);
                    MMA_BF16(cS[1][nf], a[1][0], a[1][1], a[1][2], a[1][3], b0, b1);
                }
            }
        }
        #pragma unroll
        for (int mt = 0; mt < 2; mt++) {
            int row = wm + mt * 16 + lr;
            #pragma unroll
            for (int nf = 0; nf < 8; nf++) {
                int tc = nf * 8 + lc * 2;
                *(float2*)(sf + O_S + row * ASW + tc) =
                    make_float2(cS[mt][nf][0], cS[mt][nf][1]);
                *(float2*)(sf + O_S + (row + 8) * ASW + tc) =
                    make_float2(cS[mt][nf][2], cS[mt][nf][3]);
            }
        }
        __syncthreads();

        float p[64];
        float cmax = -INFINITY;
        #pragma unroll
        for (int j = 0; j < 64; j++) {
            float s = sf[O_S + t * ASW + j] * 0.125f;
            int tok = w * WIN + c * 64 + j - OV;
            if (!qv) s = -1.25e9f;
            if ((unsigned)tok >= (unsigned)LSEQ) s = -INFINITY;
            p[j] = s;
            cmax = fmaxf(cmax, s);
        }
        const float mn = fmaxf(m, cmax);
        const float corr = __expf(m - mn);
        l *= corr;
        float ls = 0.f;
        #pragma unroll
        for (int j = 0; j < 64; j++) { p[j] = __expf(p[j] - mn); ls += p[j]; }
        l += ls;
        m = mn;
        sf[O_CR + t] = corr;
        #pragma unroll
        for (int j = 0; j < 32; j++) {
            uint2 ww = splitW(p[2 * j], p[2 * j + 1]);
            sw[O_S + t * ASW + j]      = ww.x;
            sw[O_S + t * ASW + 32 + j] = ww.y;
        }
        __syncthreads();

        #pragma unroll
        for (int mt = 0; mt < 2; mt++) {
            float c0 = sf[O_CR + wm + mt * 16 + lr];
            float c1 = sf[O_CR + wm + mt * 16 + lr + 8];
            #pragma unroll
            for (int nf = 0; nf < 8; nf++) {
                cO[mt][nf][0] *= c0; cO[mt][nf][1] *= c0;
                cO[mt][nf][2] *= c1; cO[mt][nf][3] *= c1;
            }
        }
        #pragma unroll
        for (int pass = 0; pass < 3; pass++) {
            const int ab = O_S + ((pass == 1) ? 32 : 0);
            const int bb = (pass == 2) ? O_VL : O_VH;
            #pragma unroll
            for (int ks = 0; ks < 4; ks++) {
                uint32_t a[2][4];
                #pragma unroll
                for (int mt = 0; mt < 2; mt++) {
                    int base = ab + (wm + mt * 16 + lr) * ASW + ks * 8 + lc;
                    a[mt][0] = sw[base];
                    a[mt][1] = sw[base + 8 * ASW];
                    a[mt][2] = sw[base + 4];
                    a[mt][3] = sw[base + 8 * ASW + 4];
                }
                #pragma unroll
                for (int nf = 0; nf < 8; nf++) {
                    int bbase = bb + (nf * 8 + lr) * AQW + ks * 8 + lc;
                    uint32_t b0 = sw[bbase], b1 = sw[bbase + 4];
                    MMA_BF16(cO[0][nf], a[0][0], a[0][1], a[0][2], a[0][3], b0, b1);
                    MMA_BF16(cO[1][nf], a[1][0], a[1][1], a[1][2], a[1][3], b0, b1);
                }
            }
        }
    }

    // ---- finalize: 1/l, split to bf16 planes, store ----
    const float inv = (l > 0.f) ? (1.f / l) : 0.f;
    __syncthreads();
    sf[O_CR + t] = inv;
    __syncthreads();
    #pragma unroll
    for (int mt = 0; mt < 2; mt++) {
        const int r = wm + mt * 16 + lr;
        const float i0 = sf[O_CR + r], i1 = sf[O_CR + r + 8];
        #pragma unroll
        for (int nf = 0; nf < 8; nf++) {
            const int col = h * HD + nf * 8 + lc * 2;
            uint2 s0 = splitW(cO[mt][nf][0] * i0, cO[mt][nf][1] * i0);
            uint2 s1 = splitW(cO[mt][nf][2] * i1, cO[mt][nf][3] * i1);
            const size_t p0 = ((qbase + r) * EMB + col) >> 1;
            const size_t p1 = ((qbase + r + 8) * EMB + col) >> 1;
            g_ahp[p0] = s0.x;  g_alp[p0] = s0.y;
            g_ahp[p1] = s1.x;  g_alp[p1] = s1.y;
        }
    }
}

// ---------------------------------------------------------------------------
// Kernel 3: output projection, bf16x3 (C = Ah Bh + Al Bh + Ah Bl).
// Operands pre-split into packed bf16 planes; cp.async 3-stage pipeline.
// Tile 128x128, BK=32 bf16/plane per row (16 words), XOR swizzle.
// grid: (8, 128), block 256, 2 CTAs/SM.
// ---------------------------------------------------------------------------
#define GKT       32                   // 1024 / 32 k-tiles
#define PL_W      2048                 // words per plane tile (128 rows x 16)
#define STG_W     (4 * PL_W)           // Ah, Al, Bh, Bl
#define SMEM_GEMM (3 * STG_W * 4)      // 98,304 B
#define SWZ(r)    ((((r) >> 1) & 3) << 2)

__global__ __launch_bounds__(256, 2) void out_gemm_bf16(
    const float* __restrict__ bf, float* __restrict__ out)
{
    extern __shared__ uint32_t su[];
    const uint32_t sb = smem_u32(su);
    const int tid  = threadIdx.x, lane = tid & 31, wid = tid >> 5;
    const int wm   = (wid & 1) * 64;
    const int wn   = (wid >> 1) * 32;
    const size_t m0 = (size_t)blockIdx.y * 128;
    const int e0   = blockIdx.x * 128;
    const int lr = lane >> 2, lc = lane & 3;
    const int frow = tid >> 2, fc = tid & 3;

    float c[4][4][4];
    #pragma unroll
    for (int i = 0; i < 4; i++)
        #pragma unroll
        for (int j = 0; j < 4; j++)
            #pragma unroll
            for (int u = 0; u < 4; u++) c[i][j][u] = 0.f;

    const char* pAh = (const char*)g_ahp;
    const char* pAl = (const char*)g_alp;
    const char* pBh = (const char*)g_wfh;
    const char* pBl = (const char*)g_wfl;

    auto issue = [&](int s) {
        const uint32_t stw = (uint32_t)(s % 3) * STG_W;
        #pragma unroll
        for (int rt = 0; rt < 2; rt++) {
            const int row = frow + rt * 64;
            const uint32_t offw = (uint32_t)row * 16u + ((uint32_t)(fc * 4) ^ SWZ(row));
            const size_t gA = (size_t)(m0 + row) * 2048 + (size_t)s * 64 + fc * 16;
            const size_t gB = (size_t)(e0 + row) * 2048 + (size_t)s * 64 + fc * 16;
            cp_async16(sb + (stw + offw) * 4,            pAh + gA);
            cp_async16(sb + (stw + PL_W + offw) * 4,     pAl + gA);
            cp_async16(sb + (stw + 2 * PL_W + offw) * 4, pBh + gB);
            cp_async16(sb + (stw + 3 * PL_W + offw) * 4, pBl + gB);
        }
        CP_COMMIT();
    };

    issue(0);
    issue(1);

    for (int t = 0; t < GKT; t++) {
        if (t < GKT - 1) { CP_WAIT(1); } else { CP_WAIT(0); }
        __syncthreads();
        if (t + 2 < GKT) issue(t + 2);

        const uint32_t stw = (uint32_t)(t % 3) * STG_W;
        #pragma unroll
        for (int ks = 0; ks < 2; ks++) {
            const int wl = ks * 8;
            uint32_t ah[4][4], al[4][4];
            #pragma unroll
            for (int mt = 0; mt < 4; mt++) {
                const int row = wm + mt * 16 + lr;
                const uint32_t i0 = stw + (uint32_t)row * 16u +
                                    ((uint32_t)(wl + lc) ^ SWZ(row));
                const uint32_t i2 = stw + (uint32_t)row * 16u +
                                    ((uint32_t)(wl + lc + 4) ^ SWZ(row));
                ah[mt][0] = su[i0];            ah[mt][1] = su[i0 + 128];
                ah[mt][2] = su[i2];            ah[mt][3] = su[i2 + 128];
                al[mt][0] = su[PL_W + i0];     al[mt][1] = su[PL_W + i0 + 128];
                al[mt][2] = su[PL_W + i2];     al[mt][3] = su[PL_W + i2 + 128];
            }
            #pragma unroll
            for (int nf = 0; nf < 4; nf++) {
                const int n = wn + nf * 8 + lr;
                const uint32_t j0 = stw + (uint32_t)n * 16u +
                                    ((uint32_t)(wl + lc) ^ SWZ(n));
                const uint32_t j1 = stw + (uint32_t)n * 16u +
                                    ((uint32_t)(wl + lc + 4) ^ SWZ(n));
                const uint32_t bh0 = su[2 * PL_W + j0], bh1 = su[2 * PL_W + j1];
                const uint32_t bl0 = su[3 * PL_W + j0], bl1 = su[3 * PL_W + j1];
                #pragma unroll
                for (int mt = 0; mt < 4; mt++) {
                    MMA_BF16(c[mt][nf], ah[mt][0], ah[mt][1], ah[mt][2], ah[mt][3], bh0, bh1);
                    MMA_BF16(c[mt][nf], al[mt][0], al[mt][1], al[mt][2], al[mt][3], bh0, bh1);
                    MMA_BF16(c[mt][nf], ah[mt][0], ah[mt][1], ah[mt][2], ah[mt][3], bl0, bl1);
                }
            }
        }
        __syncthreads();
    }

    #pragma unroll
    for (int mt = 0; mt < 4; mt++) {
        #pragma unroll
        for (int nf = 0; nf < 4; nf++) {
            const int mr  = (int)m0 + wm + mt * 16 + lr;
            const int col = e0 + wn + nf * 8 + lc * 2;
            const float b0 = bf[col], b1 = bf[col + 1];
            *(float2*)&out[(size_t)mr * EMB + col] =
                make_float2(c[mt][nf][0] + b0, c[mt][nf][1] + b1);
            *(float2*)&out[(size_t)(mr + 8) * EMB + col] =
                make_float2(c[mt][nf][2] + b0, c[mt][nf][3] + b1);
        }
    }
}

// ---------------------------------------------------------------------------
extern "C" void kernel_launch(void* const* d_in, const int* in_sizes, int n_in,
                              void* d_out, int out_size)
{
    const float* vals = (const float*)d_in[0];
    const float* keys = (const float*)d_in[1];
    const float* qrs  = (const float*)d_in[2];
    const int*   mask = (const int*)d_in[3];
    const float* Wv   = (const float*)d_in[4];
    const float* Wk   = (const float*)d_in[5];
    const float* Wq   = (const float*)d_in[6];
    const float* Wf   = (const float*)d_in[7];
    const float* bf   = (const float*)d_in[8];
    float* out = (float*)d_out;

    cudaFuncSetAttribute(attn_mma,
                         cudaFuncAttributeMaxDynamicSharedMemorySize, ATT_SMEM);
    cudaFuncSetAttribute(out_gemm_bf16,
                         cudaFuncAttributeMaxDynamicSharedMemorySize, SMEM_GEMM);

    proj_kernel<<<dim3(NB * LSEQ / 64, NH, 3), 256>>>(vals, keys, qrs, Wv, Wk, Wq);
    wf_split_kernel<<<EMB * EMB / 512, 256>>>(Wf);
    attn_mma<<<dim3(NWIN, NH, NB), 256, ATT_SMEM>>>(mask);
    out_gemm_bf16<<<dim3(EMB / 128, NB * LSEQ / 128), 256, SMEM_GEMM>>>(bf, out);
}

// round 14
// speedup vs baseline: 1.3349x; 1.0059x over previous
#include <cuda_runtime.h>
#include <math.h>
#include <stdint.h>

#define NB   4
#define LSEQ 4096
#define EMB  1024
#define NH   16
#define HD   64
#define WIN  256
#define OV   32
#define NWIN 16

// ---- device scratch (packed bf16x2 plane words) ----
__device__ uint32_t g_qh[(size_t)NB * LSEQ * EMB / 2];
__device__ uint32_t g_ql[(size_t)NB * LSEQ * EMB / 2];
__device__ uint32_t g_kh[(size_t)NB * LSEQ * EMB / 2];
__device__ uint32_t g_kl[(size_t)NB * LSEQ * EMB / 2];
// V transposed planes: idx = ((nb*NH+h)*64 + e)*2048 + token_pair
__device__ uint32_t g_vth[(size_t)NB * NH * HD * (LSEQ / 2)];
__device__ uint32_t g_vtl[(size_t)NB * NH * HD * (LSEQ / 2)];
// attention output planes (word = row*512 + col/2)
__device__ uint32_t g_ahp[(size_t)NB * LSEQ * EMB / 2];
__device__ uint32_t g_alp[(size_t)NB * LSEQ * EMB / 2];
// Wf planes
__device__ uint32_t g_wfh[(size_t)EMB * EMB / 2];
__device__ uint32_t g_wfl[(size_t)EMB * EMB / 2];

// ===========================================================================
__device__ __forceinline__ uint32_t smem_u32(const void* p) {
    uint32_t a;
    asm("{ .reg .u64 t; cvta.to.shared.u64 t, %1; cvt.u32.u64 %0, t; }"
        : "=r"(a) : "l"(p));
    return a;
}
__device__ __forceinline__ void cp_async16(uint32_t s, const void* g) {
    asm volatile("cp.async.cg.shared.global [%0], [%1], 16;" :: "r"(s), "l"(g));
}
// zero-fills when sz == 0 (bytes beyond src-size are zeroed)
__device__ __forceinline__ void cp_async16z(uint32_t s, const void* g, uint32_t sz) {
    asm volatile("cp.async.cg.shared.global [%0], [%1], 16, %2;"
                 :: "r"(s), "l"(g), "r"(sz));
}
#define CP_COMMIT() asm volatile("cp.async.commit_group;" ::: "memory")
#define CP_WAIT(N)  asm volatile("cp.async.wait_group %0;" :: "n"(N) : "memory")

__device__ __forceinline__ uint32_t bf16_rn_bits(float x) {
    uint32_t xi = __float_as_uint(x);
    return (xi + 0x7FFFu + ((xi >> 16) & 1u)) >> 16;
}
// split two k-consecutive floats -> {hi|hi, lo|lo} packed bf16x2 words
__device__ __forceinline__ uint2 splitW(float x, float y) {
    uint32_t xi = __float_as_uint(x), yi = __float_as_uint(y);
    float rx = x - __uint_as_float(xi & 0xFFFF0000u);
    float ry = y - __uint_as_float(yi & 0xFFFF0000u);
    return make_uint2((xi >> 16) | ((yi >> 16) << 16),
                      bf16_rn_bits(rx) | (bf16_rn_bits(ry) << 16));
}

#define MMA_BF16(c, a0, a1, a2, a3, b0, b1) \
    asm volatile("mma.sync.aligned.m16n8k16.row.col.f32.bf16.bf16.f32 " \
                 "{%0,%1,%2,%3}, {%4,%5,%6,%7}, {%8,%9}, {%0,%1,%2,%3};" \
                 : "+f"((c)[0]), "+f"((c)[1]), "+f"((c)[2]), "+f"((c)[3]) \
                 : "r"(a0), "r"(a1), "r"(a2), "r"(a3), "r"(b0), "r"(b1))

// ---------------------------------------------------------------------------
// Kernel 1: q/k/v projection via bf16x3 mma. Writes q/k split planes and
// V transposed split planes. grid (128, NH, 3), block 256 (8 warps x 16 rows).
// smem words: XH 0, XL 4608, WH 9216, WL 11520 (stride 36 word rows).
// ---------------------------------------------------------------------------
#define PJW 36
#define PJ_XH 0
#define PJ_XL 4608
#define PJ_WH 9216
#define PJ_WL 11520
#define PJ_SMEM (13824 * 4)

__global__ __launch_bounds__(256) void proj_mma(
    const float* __restrict__ vals, const float* __restrict__ keys,
    const float* __restrict__ qrs,
    const float* __restrict__ Wv, const float* __restrict__ Wk,
    const float* __restrict__ Wq)
{
    extern __shared__ uint32_t ps[];
    const int t = threadIdx.x, lane = t & 31, wid = t >> 5;
    const int lr = lane >> 2, lc = lane & 3;
    const int h = blockIdx.y, which = blockIdx.z;
    const size_t r0 = (size_t)blockIdx.x * 128;

    const float* X; const float* W;
    switch (which) {
        case 0:  X = vals; W = Wv; break;
        case 1:  X = keys; W = Wk; break;
        default: X = qrs;  W = Wq; break;
    }

    // load + split W (64x64) and X tile (128x64)
    for (int i = t; i < 1024; i += 256) {
        int r = i >> 4, g = i & 15;
        float4 v = *(const float4*)&W[r * 64 + g * 4];
        uint2 s01 = splitW(v.x, v.y), s23 = splitW(v.z, v.w);
        ps[PJ_WH + r * PJW + g * 2]     = s01.x;
        ps[PJ_WH + r * PJW + g * 2 + 1] = s23.x;
        ps[PJ_WL + r * PJW + g * 2]     = s01.y;
        ps[PJ_WL + r * PJW + g * 2 + 1] = s23.y;
    }
    for (int i = t; i < 2048; i += 256) {
        int r = i >> 4, g = i & 15;
        float4 v = *(const float4*)&X[(r0 + r) * EMB + h * HD + g * 4];
        uint2 s01 = splitW(v.x, v.y), s23 = splitW(v.z, v.w);
        ps[PJ_XH + r * PJW + g * 2]     = s01.x;
        ps[PJ_XH + r * PJW + g * 2 + 1] = s23.x;
        ps[PJ_XL + r * PJW + g * 2]     = s01.y;
        ps[PJ_XL + r * PJW + g * 2 + 1] = s23.y;
    }
    __syncthreads();

    const int am = wid * 16;
    float c[8][4];
    #pragma unroll
    for (int nf = 0; nf < 8; nf++)
        #pragma unroll
        for (int u = 0; u < 4; u++) c[nf][u] = 0.f;

    #pragma unroll
    for (int pass = 0; pass < 3; pass++) {
        const int ab = (pass == 1) ? PJ_XL : PJ_XH;
        const int bb = (pass == 2) ? PJ_WL : PJ_WH;
        #pragma unroll
        for (int kt = 0; kt < 4; kt++) {
            const int abase = ab + (am + lr) * PJW + kt * 8 + lc;
            uint32_t a0 = ps[abase],     a1 = ps[abase + 8 * PJW];
            uint32_t a2 = ps[abase + 4], a3 = ps[abase + 8 * PJW + 4];
            #pragma unroll
            for (int nf = 0; nf < 8; nf++) {
                const int bbase = bb + (nf * 8 + lr) * PJW + kt * 8 + lc;
                MMA_BF16(c[nf], a0, a1, a2, a3, ps[bbase], ps[bbase + 4]);
            }
        }
    }

    if (which >= 1) {
        uint32_t* ph = (which == 2) ? g_qh : g_kh;
        uint32_t* pl = (which == 2) ? g_ql : g_kl;
        const size_t rg = r0 + am + lr;
        #pragma unroll
        for (int nf = 0; nf < 8; nf++) {
            const size_t wrd = rg * 512 + h * 32 + nf * 4 + lc;
            uint2 s0 = splitW(c[nf][0], c[nf][1]);
            uint2 s1 = splitW(c[nf][2], c[nf][3]);
            ph[wrd] = s0.x;              pl[wrd] = s0.y;
            ph[wrd + 8 * 512] = s1.x;    pl[wrd + 8 * 512] = s1.y;
        }
    } else {
        // stage transposed fp32: sv[e][tok_local], stride 132
        __syncthreads();
        float* sv = (float*)ps;
        #pragma unroll
        for (int nf = 0; nf < 8; nf++) {
            const int col = nf * 8 + 2 * lc;
            sv[col * 132 + am + lr]           = c[nf][0];
            sv[(col + 1) * 132 + am + lr]     = c[nf][1];
            sv[col * 132 + am + lr + 8]       = c[nf][2];
            sv[(col + 1) * 132 + am + lr + 8] = c[nf][3];
        }
        __syncthreads();
        const int nb = (int)(r0 / LSEQ);
        const size_t base = ((size_t)(nb * NH + h) * 64) * 2048 + (r0 % LSEQ) / 2;
        const int tp = t & 63, e0 = t >> 6;
        #pragma unroll
        for (int it = 0; it < 16; it++) {
            const int e = it * 4 + e0;
            float2 v = *(const float2*)&sv[e * 132 + 2 * tp];
            uint2 s = splitW(v.x, v.y);
            g_vth[base + (size_t)e * 2048 + tp] = s.x;
            g_vtl[base + (size_t)e * 2048 + tp] = s.y;
        }
    }
}

// ---------------------------------------------------------------------------
// Kernel 1b: split Wf into bf16 planes.
// ---------------------------------------------------------------------------
__global__ __launch_bounds__(256) void wf_split_kernel(const float* __restrict__ Wf)
{
    const int i = blockIdx.x * 256 + threadIdx.x;
    float2 v = *(const float2*)&Wf[2 * i];
    uint2 s = splitW(v.x, v.y);
    g_wfh[i] = s.x;
    g_wfl[i] = s.y;
}

// ---------------------------------------------------------------------------
// Kernel 2: attention, register softmax, cp.async double-buffered K/V planes.
// Block = (window, head, batch), 256 threads, 8 warps x 32 query rows.
// smem: 2 buffers x [Kh, Kl, Vh, Vl], each plane 64 rows x 36 words.
// ---------------------------------------------------------------------------
#define KVW (64 * 36)
#define ABUF (4 * KVW)
#define ATT_SMEM (2 * ABUF * 4)     // 73,728 B

__global__ __launch_bounds__(256, 1) void attn_mma(const int* __restrict__ mask)
{
    extern __shared__ uint32_t as_[];
    const uint32_t sb = smem_u32(as_);
    const int t = threadIdx.x, lane = t & 31, wid = t >> 5;
    const int lr = lane >> 2, lc = lane & 3;
    const int wm = wid * 32;
    const int w = blockIdx.x, h = blockIdx.y, nb = blockIdx.z;
    const size_t qbase = (size_t)nb * LSEQ + (size_t)w * WIN;

    // ---- Q fragments (registers, loaded once from planes) ----
    uint32_t qh[2][4][4], ql[2][4][4];
    #pragma unroll
    for (int mt = 0; mt < 2; mt++) {
        const size_t rw = (qbase + wm + mt * 16 + lr) * 512 + h * 32;
        #pragma unroll
        for (int kt = 0; kt < 4; kt++) {
            const size_t b0 = rw + kt * 8 + lc, b1 = b0 + 8 * 512;
            qh[mt][kt][0] = g_qh[b0];     qh[mt][kt][1] = g_qh[b1];
            qh[mt][kt][2] = g_qh[b0 + 4]; qh[mt][kt][3] = g_qh[b1 + 4];
            ql[mt][kt][0] = g_ql[b0];     ql[mt][kt][1] = g_ql[b1];
            ql[mt][kt][2] = g_ql[b0 + 4]; ql[mt][kt][3] = g_ql[b1 + 4];
        }
    }
    bool qv[2][2];
    #pragma unroll
    for (int mt = 0; mt < 2; mt++) {
        qv[mt][0] = mask[qbase + wm + mt * 16 + lr] != 0;
        qv[mt][1] = mask[qbase + wm + mt * 16 + lr + 8] != 0;
    }

    float m_[2][2], l_[2][2];
    #pragma unroll
    for (int mt = 0; mt < 2; mt++) {
        m_[mt][0] = -INFINITY; m_[mt][1] = -INFINITY;
        l_[mt][0] = 0.f;       l_[mt][1] = 0.f;
    }
    float cO[2][8][4];
    #pragma unroll
    for (int mt = 0; mt < 2; mt++)
        #pragma unroll
        for (int nf = 0; nf < 8; nf++)
            #pragma unroll
            for (int u = 0; u < 4; u++) cO[mt][nf][u] = 0.f;

    // ---- K/V plane fill via cp.async (zero-fill out of range) ----
    auto issue = [&](int c) {
        const uint32_t d0 = sb + (uint32_t)((c & 1) * ABUF) * 4u;
        for (int i = t; i < 512; i += 256) {          // K planes
            const int r = i >> 3, fc = i & 7;
            const int tok = w * WIN + c * 64 + r - OV;
            const uint32_t ok = ((unsigned)tok < (unsigned)LSEQ) ? 16u : 0u;
            const int tokc = ok ? tok : 0;
            const size_t src = (size_t)((size_t)nb * LSEQ + tokc) * 512 + h * 32 + fc * 4;
            const uint32_t dw = (uint32_t)(r * 36 + fc * 4) * 4u;
            cp_async16z(d0 + dw,               &g_kh[src], ok);
            cp_async16z(d0 + KVW * 4u + dw,    &g_kl[src], ok);
        }
        for (int i = t; i < 512; i += 256) {          // V planes (transposed)
            const int e = i >> 3, fc = i & 7;
            const int tp0 = w * (WIN / 2) + c * 32 - OV / 2 + fc * 4;
            const uint32_t ok = ((unsigned)tp0 < (unsigned)(LSEQ / 2)) ? 16u : 0u;
            const int tpc = ok ? tp0 : 0;
            const size_t src = ((size_t)(nb * NH + h) * 64 + e) * 2048 + tpc;
            const uint32_t dw = (uint32_t)(e * 36 + fc * 4) * 4u;
            cp_async16z(d0 + 2u * KVW * 4u + dw, &g_vth[src], ok);
            cp_async16z(d0 + 3u * KVW * 4u + dw, &g_vtl[src], ok);
        }
        CP_COMMIT();
    };

    issue(0);

    for (int c = 0; c < 5; c++) {
        __syncthreads();                      // all done reading buffer (c+1)&1
        if (c < 4) { issue(c + 1); CP_WAIT(1); } else { CP_WAIT(0); }
        __syncthreads();

        const uint32_t kb = (uint32_t)((c & 1) * ABUF);

        // ---- S = Q K^T (3 passes) ----
        float cS[2][8][4];
        #pragma unroll
        for (int mt = 0; mt < 2; mt++)
            #pragma unroll
            for (int nf = 0; nf < 8; nf++)
                #pragma unroll
                for (int u = 0; u < 4; u++) cS[mt][nf][u] = 0.f;

        #pragma unroll
        for (int pass = 0; pass < 3; pass++) {
            const uint32_t bo = kb + ((pass == 2) ? KVW : 0);
            #pragma unroll
            for (int kt = 0; kt < 4; kt++) {
                #pragma unroll
                for (int nf = 0; nf < 8; nf++) {
                    const uint32_t bb = bo + (nf * 8 + lr) * 36 + kt * 8 + lc;
                    const uint32_t b0 = as_[bb], b1 = as_[bb + 4];
                    if (pass == 1) {
                        MMA_BF16(cS[0][nf], ql[0][kt][0], ql[0][kt][1], ql[0][kt][2], ql[0][kt][3], b0, b1);
                        MMA_BF16(cS[1][nf], ql[1][kt][0], ql[1][kt][1], ql[1][kt][2], ql[1][kt][3], b0, b1);
                    } else {
                        MMA_BF16(cS[0][nf], qh[0][kt][0], qh[0][kt][1], qh[0][kt][2], qh[0][kt][3], b0, b1);
                        MMA_BF16(cS[1][nf], qh[1][kt][0], qh[1][kt][1], qh[1][kt][2], qh[1][kt][3], b0, b1);
                    }
                }
            }
        }

        // ---- register softmax (4-lane shuffles) ----
        const int cbase = w * WIN + c * 64 - OV;
        const bool vlo = (cbase >= 0);
        const bool vhi = (cbase + 63 < LSEQ);

        #pragma unroll
        for (int mt = 0; mt < 2; mt++) {
            float mx0 = -INFINITY, mx1 = -INFINITY;
            #pragma unroll
            for (int nf = 0; nf < 8; nf++) {
                const bool kv = (nf < 4) ? vlo : vhi;
                float x0 = cS[mt][nf][0] * 0.125f, x1 = cS[mt][nf][1] * 0.125f;
                float x2 = cS[mt][nf][2] * 0.125f, x3 = cS[mt][nf][3] * 0.125f;
                if (!qv[mt][0]) { x0 = -1.25e9f; x1 = -1.25e9f; }
                if (!qv[mt][1]) { x2 = -1.25e9f; x3 = -1.25e9f; }
                if (!kv) { x0 = -INFINITY; x1 = -INFINITY; x2 = -INFINITY; x3 = -INFINITY; }
                cS[mt][nf][0] = x0; cS[mt][nf][1] = x1;
                cS[mt][nf][2] = x2; cS[mt][nf][3] = x3;
                mx0 = fmaxf(mx0, fmaxf(x0, x1));
                mx1 = fmaxf(mx1, fmaxf(x2, x3));
            }
            mx0 = fmaxf(mx0, __shfl_xor_sync(0xffffffffu, mx0, 1));
            mx0 = fmaxf(mx0, __shfl_xor_sync(0xffffffffu, mx0, 2));
            mx1 = fmaxf(mx1, __shfl_xor_sync(0xffffffffu, mx1, 1));
            mx1 = fmaxf(mx1, __shfl_xor_sync(0xffffffffu, mx1, 2));

            const float mn0 = fmaxf(m_[mt][0], mx0);
            const float mn1 = fmaxf(m_[mt][1], mx1);
            const float cr0 = __expf(m_[mt][0] - mn0);
            const float cr1 = __expf(m_[mt][1] - mn1);
            m_[mt][0] = mn0; m_[mt][1] = mn1;

            float ls0 = 0.f, ls1 = 0.f;
            #pragma unroll
            for (int nf = 0; nf < 8; nf++) {
                const float p0 = __expf(cS[mt][nf][0] - mn0);
                const float p1 = __expf(cS[mt][nf][1] - mn0);
                const float p2 = __expf(cS[mt][nf][2] - mn1);
                const float p3 = __expf(cS[mt][nf][3] - mn1);
                cS[mt][nf][0] = p0; cS[mt][nf][1] = p1;
                cS[mt][nf][2] = p2; cS[mt][nf][3] = p3;
                ls0 += p0 + p1; ls1 += p2 + p3;
            }
            ls0 += __shfl_xor_sync(0xffffffffu, ls0, 1);
            ls0 += __shfl_xor_sync(0xffffffffu, ls0, 2);
            ls1 += __shfl_xor_sync(0xffffffffu, ls1, 1);
            ls1 += __shfl_xor_sync(0xffffffffu, ls1, 2);
            l_[mt][0] = l_[mt][0] * cr0 + ls0;
            l_[mt][1] = l_[mt][1] * cr1 + ls1;

            #pragma unroll
            for (int nf = 0; nf < 8; nf++) {
                cO[mt][nf][0] *= cr0; cO[mt][nf][1] *= cr0;
                cO[mt][nf][2] *= cr1; cO[mt][nf][3] *= cr1;
            }
        }

        // ---- O += P V (P fragments direct from cS; 3 passes) ----
        #pragma unroll
        for (int kt = 0; kt < 4; kt++) {
            uint32_t phi[2][4], plo[2][4];
            #pragma unroll
            for (int mt = 0; mt < 2; mt++) {
                uint2 s0 = splitW(cS[mt][2 * kt][0],     cS[mt][2 * kt][1]);
                uint2 s1 = splitW(cS[mt][2 * kt][2],     cS[mt][2 * kt][3]);
                uint2 s2 = splitW(cS[mt][2 * kt + 1][0], cS[mt][2 * kt + 1][1]);
                uint2 s3 = splitW(cS[mt][2 * kt + 1][2], cS[mt][2 * kt + 1][3]);
                phi[mt][0] = s0.x; plo[mt][0] = s0.y;
                phi[mt][1] = s1.x; plo[mt][1] = s1.y;
                phi[mt][2] = s2.x; plo[mt][2] = s2.y;
                phi[mt][3] = s3.x; plo[mt][3] = s3.y;
            }
            #pragma unroll
            for (int nf = 0; nf < 8; nf++) {
                const uint32_t hb = kb + 2 * KVW + (nf * 8 + lr) * 36 + kt * 8 + lc;
                const uint32_t lb = hb + KVW;
                const uint32_t bh0 = as_[hb], bh1 = as_[hb + 4];
                const uint32_t bl0 = as_[lb], bl1 = as_[lb + 4];
                #pragma unroll
                for (int mt = 0; mt < 2; mt++) {
                    MMA_BF16(cO[mt][nf], phi[mt][0], phi[mt][1], phi[mt][2], phi[mt][3], bh0, bh1);
                    MMA_BF16(cO[mt][nf], plo[mt][0], plo[mt][1], plo[mt][2], plo[mt][3], bh0, bh1);
                    MMA_BF16(cO[mt][nf], phi[mt][0], phi[mt][1], phi[mt][2], phi[mt][3], bl0, bl1);
                }
            }
        }
    }

    // ---- epilogue: 1/l, split to planes, store ----
    #pragma unroll
    for (int mt = 0; mt < 2; mt++) {
        const float i0 = (l_[mt][0] > 0.f) ? (1.f / l_[mt][0]) : 0.f;
        const float i1 = (l_[mt][1] > 0.f) ? (1.f / l_[mt][1]) : 0.f;
        const size_t rw = (qbase + wm + mt * 16 + lr) * 512 + h * 32;
        #pragma unroll
        for (int nf = 0; nf < 8; nf++) {
            const size_t wrd = rw + nf * 4 + lc;
            uint2 s0 = splitW(cO[mt][nf][0] * i0, cO[mt][nf][1] * i0);
            uint2 s1 = splitW(cO[mt][nf][2] * i1, cO[mt][nf][3] * i1);
            g_ahp[wrd] = s0.x;              g_alp[wrd] = s0.y;
            g_ahp[wrd + 8 * 512] = s1.x;    g_alp[wrd + 8 * 512] = s1.y;
        }
    }
}

// ---------------------------------------------------------------------------
// Kernel 3: output projection, bf16x3 (unchanged from R13, 255us, tensor 66%).
// ---------------------------------------------------------------------------
#define GKT       32
#define PL_W      2048
#define STG_W     (4 * PL_W)
#define SMEM_GEMM (3 * STG_W * 4)
#define SWZ(r)    ((((r) >> 1) & 3) << 2)

__global__ __launch_bounds__(256, 2) void out_gemm_bf16(
    const float* __restrict__ bf, float* __restrict__ out)
{
    extern __shared__ uint32_t su[];
    const uint32_t sb = smem_u32(su);
    const int tid  = threadIdx.x, lane = tid & 31, wid = tid >> 5;
    const int wm   = (wid & 1) * 64;
    const int wn   = (wid >> 1) * 32;
    const size_t m0 = (size_t)blockIdx.y * 128;
    const int e0   = blockIdx.x * 128;
    const int lr = lane >> 2, lc = lane & 3;
    const int frow = tid >> 2, fc = tid & 3;

    float c[4][4][4];
    #pragma unroll
    for (int i = 0; i < 4; i++)
        #pragma unroll
        for (int j = 0; j < 4; j++)
            #pragma unroll
            for (int u = 0; u < 4; u++) c[i][j][u] = 0.f;

    const char* pAh = (const char*)g_ahp;
    const char* pAl = (const char*)g_alp;
    const char* pBh = (const char*)g_wfh;
    const char* pBl = (const char*)g_wfl;

    auto issue = [&](int s) {
        const uint32_t stw = (uint32_t)(s % 3) * STG_W;
        #pragma unroll
        for (int rt = 0; rt < 2; rt++) {
            const int row = frow + rt * 64;
            const uint32_t offw = (uint32_t)row * 16u + ((uint32_t)(fc * 4) ^ SWZ(row));
            const size_t gA = (size_t)(m0 + row) * 2048 + (size_t)s * 64 + fc * 16;
            const size_t gB = (size_t)(e0 + row) * 2048 + (size_t)s * 64 + fc * 16;
            cp_async16(sb + (stw + offw) * 4,            pAh + gA);
            cp_async16(sb + (stw + PL_W + offw) * 4,     pAl + gA);
            cp_async16(sb + (stw + 2 * PL_W + offw) * 4, pBh + gB);
            cp_async16(sb + (stw + 3 * PL_W + offw) * 4, pBl + gB);
        }
        CP_COMMIT();
    };

    issue(0);
    issue(1);

    for (int t = 0; t < GKT; t++) {
        if (t < GKT - 1) { CP_WAIT(1); } else { CP_WAIT(0); }
        __syncthreads();
        if (t + 2 < GKT) issue(t + 2);

        const uint32_t stw = (uint32_t)(t % 3) * STG_W;
        #pragma unroll
        for (int ks = 0; ks < 2; ks++) {
            const int wl = ks * 8;
            uint32_t ah[4][4], al[4][4];
            #pragma unroll
            for (int mt = 0; mt < 4; mt++) {
                const int row = wm + mt * 16 + lr;
                const uint32_t i0 = stw + (uint32_t)row * 16u +
                                    ((uint32_t)(wl + lc) ^ SWZ(row));
                const uint32_t i2 = stw + (uint32_t)row * 16u +
                                    ((uint32_t)(wl + lc + 4) ^ SWZ(row));
                ah[mt][0] = su[i0];            ah[mt][1] = su[i0 + 128];
                ah[mt][2] = su[i2];            ah[mt][3] = su[i2 + 128];
                al[mt][0] = su[PL_W + i0];     al[mt][1] = su[PL_W + i0 + 128];
                al[mt][2] = su[PL_W + i2];     al[mt][3] = su[PL_W + i2 + 128];
            }
            #pragma unroll
            for (int nf = 0; nf < 4; nf++) {
                const int n = wn + nf * 8 + lr;
                const uint32_t j0 = stw + (uint32_t)n * 16u +
                                    ((uint32_t)(wl + lc) ^ SWZ(n));
                const uint32_t j1 = stw + (uint32_t)n * 16u +
                                    ((uint32_t)(wl + lc + 4) ^ SWZ(n));
                const uint32_t bh0 = su[2 * PL_W + j0], bh1 = su[2 * PL_W + j1];
                const uint32_t bl0 = su[3 * PL_W + j0], bl1 = su[3 * PL_W + j1];
                #pragma unroll
                for (int mt = 0; mt < 4; mt++) {
                    MMA_BF16(c[mt][nf], ah[mt][0], ah[mt][1], ah[mt][2], ah[mt][3], bh0, bh1);
                    MMA_BF16(c[mt][nf], al[mt][0], al[mt][1], al[mt][2], al[mt][3], bh0, bh1);
                    MMA_BF16(c[mt][nf], ah[mt][0], ah[mt][1], ah[mt][2], ah[mt][3], bl0, bl1);
                }
            }
        }
        __syncthreads();
    }

    #pragma unroll
    for (int mt = 0; mt < 4; mt++) {
        #pragma unroll
        for (int nf = 0; nf < 4; nf++) {
            const int mr  = (int)m0 + wm + mt * 16 + lr;
            const int col = e0 + wn + nf * 8 + lc * 2;
            const float b0 = bf[col], b1 = bf[col + 1];
            *(float2*)&out[(size_t)mr * EMB + col] =
                make_float2(c[mt][nf][0] + b0, c[mt][nf][1] + b1);
            *(float2*)&out[(size_t)(mr + 8) * EMB + col] =
                make_float2(c[mt][nf][2] + b0, c[mt][nf][3] + b1);
        }
    }
}

// ---------------------------------------------------------------------------
extern "C" void kernel_launch(void* const* d_in, const int* in_sizes, int n_in,
                              void* d_out, int out_size)
{
    const float* vals = (const float*)d_in[0];
    const float* keys = (const float*)d_in[1];
    const float* qrs  = (const float*)d_in[2];
    const int*   mask = (const int*)d_in[3];
    const float* Wv   = (const float*)d_in[4];
    const float* Wk   = (const float*)d_in[5];
    const float* Wq   = (const float*)d_in[6];
    const float* Wf   = (const float*)d_in[7];
    const float* bf   = (const float*)d_in[8];
    float* out = (float*)d_out;

    cudaFuncSetAttribute(proj_mma,
                         cudaFuncAttributeMaxDynamicSharedMemorySize, PJ_SMEM);
    cudaFuncSetAttribute(attn_mma,
                         cudaFuncAttributeMaxDynamicSharedMemorySize, ATT_SMEM);
    cudaFuncSetAttribute(out_gemm_bf16,
                         cudaFuncAttributeMaxDynamicSharedMemorySize, SMEM_GEMM);

    proj_mma<<<dim3(NB * LSEQ / 128, NH, 3), 256, PJ_SMEM>>>(vals, keys, qrs, Wv, Wk, Wq);
    wf_split_kernel<<<EMB * EMB / 512, 256>>>(Wf);
    attn_mma<<<dim3(NWIN, NH, NB), 256, ATT_SMEM>>>(mask);
    out_gemm_bf16<<<dim3(EMB / 128, NB * LSEQ / 128), 256, SMEM_GEMM>>>(bf, out);
}

// round 15
// speedup vs baseline: 1.8738x; 1.4037x over previous
#include <cuda_runtime.h>
#include <math.h>
#include <stdint.h>

#define NB   4
#define LSEQ 4096
#define EMB  1024
#define NH   16
#define HD   64
#define WIN  256
#define OV   32
#define NWIN 16

// ---- device scratch (packed bf16x2 plane words) ----
__device__ uint32_t g_qh[(size_t)NB * LSEQ * EMB / 2];
__device__ uint32_t g_ql[(size_t)NB * LSEQ * EMB / 2];
__device__ uint32_t g_kh[(size_t)NB * LSEQ * EMB / 2];
__device__ uint32_t g_kl[(size_t)NB * LSEQ * EMB / 2];
// V transposed planes: idx = ((nb*NH+h)*64 + e)*2048 + token_pair
__device__ uint32_t g_vth[(size_t)NB * NH * HD * (LSEQ / 2)];
__device__ uint32_t g_vtl[(size_t)NB * NH * HD * (LSEQ / 2)];
// attention output planes (word = row*512 + col/2)
__device__ uint32_t g_ahp[(size_t)NB * LSEQ * EMB / 2];
__device__ uint32_t g_alp[(size_t)NB * LSEQ * EMB / 2];
// Wf planes
__device__ uint32_t g_wfh[(size_t)EMB * EMB / 2];
__device__ uint32_t g_wfl[(size_t)EMB * EMB / 2];

// ===========================================================================
__device__ __forceinline__ uint32_t smem_u32(const void* p) {
    uint32_t a;
    asm("{ .reg .u64 t; cvta.to.shared.u64 t, %1; cvt.u32.u64 %0, t; }"
        : "=r"(a) : "l"(p));
    return a;
}
__device__ __forceinline__ void cp_async16(uint32_t s, const void* g) {
    asm volatile("cp.async.cg.shared.global [%0], [%1], 16;" :: "r"(s), "l"(g));
}
__device__ __forceinline__ void cp_async16z(uint32_t s, const void* g, uint32_t sz) {
    asm volatile("cp.async.cg.shared.global [%0], [%1], 16, %2;"
                 :: "r"(s), "l"(g), "r"(sz));
}
#define CP_COMMIT() asm volatile("cp.async.commit_group;" ::: "memory")
#define CP_WAIT(N)  asm volatile("cp.async.wait_group %0;" :: "n"(N) : "memory")

__device__ __forceinline__ uint32_t bf16_rn_bits(float x) {
    uint32_t xi = __float_as_uint(x);
    return (xi + 0x7FFFu + ((xi >> 16) & 1u)) >> 16;
}
__device__ __forceinline__ uint2 splitW(float x, float y) {
    uint32_t xi = __float_as_uint(x), yi = __float_as_uint(y);
    float rx = x - __uint_as_float(xi & 0xFFFF0000u);
    float ry = y - __uint_as_float(yi & 0xFFFF0000u);
    return make_uint2((xi >> 16) | ((yi >> 16) << 16),
                      bf16_rn_bits(rx) | (bf16_rn_bits(ry) << 16));
}

#define MMA_BF16(c, a0, a1, a2, a3, b0, b1) \
    asm volatile("mma.sync.aligned.m16n8k16.row.col.f32.bf16.bf16.f32 " \
                 "{%0,%1,%2,%3}, {%4,%5,%6,%7}, {%8,%9}, {%0,%1,%2,%3};" \
                 : "+f"((c)[0]), "+f"((c)[1]), "+f"((c)[2]), "+f"((c)[3]) \
                 : "r"(a0), "r"(a1), "r"(a2), "r"(a3), "r"(b0), "r"(b1))

#define LDM_X4(r0, r1, r2, r3, addr) \
    asm volatile("ldmatrix.sync.aligned.m8n8.x4.shared.b16 {%0,%1,%2,%3}, [%4];" \
                 : "=r"(r0), "=r"(r1), "=r"(r2), "=r"(r3) : "r"(addr))

// ---------------------------------------------------------------------------
// Kernel 1: q/k/v projection via bf16x3 mma (unchanged from R14).
// ---------------------------------------------------------------------------
#define PJW 36
#define PJ_XH 0
#define PJ_XL 4608
#define PJ_WH 9216
#define PJ_WL 11520
#define PJ_SMEM (13824 * 4)

__global__ __launch_bounds__(256) void proj_mma(
    const float* __restrict__ vals, const float* __restrict__ keys,
    const float* __restrict__ qrs,
    const float* __restrict__ Wv, const float* __restrict__ Wk,
    const float* __restrict__ Wq)
{
    extern __shared__ uint32_t ps[];
    const int t = threadIdx.x, lane = t & 31, wid = t >> 5;
    const int lr = lane >> 2, lc = lane & 3;
    const int h = blockIdx.y, which = blockIdx.z;
    const size_t r0 = (size_t)blockIdx.x * 128;

    const float* X; const float* W;
    switch (which) {
        case 0:  X = vals; W = Wv; break;
        case 1:  X = keys; W = Wk; break;
        default: X = qrs;  W = Wq; break;
    }

    for (int i = t; i < 1024; i += 256) {
        int r = i >> 4, g = i & 15;
        float4 v = *(const float4*)&W[r * 64 + g * 4];
        uint2 s01 = splitW(v.x, v.y), s23 = splitW(v.z, v.w);
        ps[PJ_WH + r * PJW + g * 2]     = s01.x;
        ps[PJ_WH + r * PJW + g * 2 + 1] = s23.x;
        ps[PJ_WL + r * PJW + g * 2]     = s01.y;
        ps[PJ_WL + r * PJW + g * 2 + 1] = s23.y;
    }
    for (int i = t; i < 2048; i += 256) {
        int r = i >> 4, g = i & 15;
        float4 v = *(const float4*)&X[(r0 + r) * EMB + h * HD + g * 4];
        uint2 s01 = splitW(v.x, v.y), s23 = splitW(v.z, v.w);
        ps[PJ_XH + r * PJW + g * 2]     = s01.x;
        ps[PJ_XH + r * PJW + g * 2 + 1] = s23.x;
        ps[PJ_XL + r * PJW + g * 2]     = s01.y;
        ps[PJ_XL + r * PJW + g * 2 + 1] = s23.y;
    }
    __syncthreads();

    const int am = wid * 16;
    float c[8][4];
    #pragma unroll
    for (int nf = 0; nf < 8; nf++)
        #pragma unroll
        for (int u = 0; u < 4; u++) c[nf][u] = 0.f;

    #pragma unroll
    for (int pass = 0; pass < 3; pass++) {
        const int ab = (pass == 1) ? PJ_XL : PJ_XH;
        const int bb = (pass == 2) ? PJ_WL : PJ_WH;
        #pragma unroll
        for (int kt = 0; kt < 4; kt++) {
            const int abase = ab + (am + lr) * PJW + kt * 8 + lc;
            uint32_t a0 = ps[abase],     a1 = ps[abase + 8 * PJW];
            uint32_t a2 = ps[abase + 4], a3 = ps[abase + 8 * PJW + 4];
            #pragma unroll
            for (int nf = 0; nf < 8; nf++) {
                const int bbase = bb + (nf * 8 + lr) * PJW + kt * 8 + lc;
                MMA_BF16(c[nf], a0, a1, a2, a3, ps[bbase], ps[bbase + 4]);
            }
        }
    }

    if (which >= 1) {
        uint32_t* ph = (which == 2) ? g_qh : g_kh;
        uint32_t* pl = (which == 2) ? g_ql : g_kl;
        const size_t rg = r0 + am + lr;
        #pragma unroll
        for (int nf = 0; nf < 8; nf++) {
            const size_t wrd = rg * 512 + h * 32 + nf * 4 + lc;
            uint2 s0 = splitW(c[nf][0], c[nf][1]);
            uint2 s1 = splitW(c[nf][2], c[nf][3]);
            ph[wrd] = s0.x;              pl[wrd] = s0.y;
            ph[wrd + 8 * 512] = s1.x;    pl[wrd + 8 * 512] = s1.y;
        }
    } else {
        __syncthreads();
        float* sv = (float*)ps;
        #pragma unroll
        for (int nf = 0; nf < 8; nf++) {
            const int col = nf * 8 + 2 * lc;
            sv[col * 132 + am + lr]           = c[nf][0];
            sv[(col + 1) * 132 + am + lr]     = c[nf][1];
            sv[col * 132 + am + lr + 8]       = c[nf][2];
            sv[(col + 1) * 132 + am + lr + 8] = c[nf][3];
        }
        __syncthreads();
        const int nb = (int)(r0 / LSEQ);
        const size_t base = ((size_t)(nb * NH + h) * 64) * 2048 + (r0 % LSEQ) / 2;
        const int tp = t & 63, e0 = t >> 6;
        #pragma unroll
        for (int it = 0; it < 16; it++) {
            const int e = it * 4 + e0;
            float2 v = *(const float2*)&sv[e * 132 + 2 * tp];
            uint2 s = splitW(v.x, v.y);
            g_vth[base + (size_t)e * 2048 + tp] = s.x;
            g_vtl[base + (size_t)e * 2048 + tp] = s.y;
        }
    }
}

// ---------------------------------------------------------------------------
// Kernel 1b: split Wf into bf16 planes.
// ---------------------------------------------------------------------------
__global__ __launch_bounds__(256) void wf_split_kernel(const float* __restrict__ Wf)
{
    const int i = blockIdx.x * 256 + threadIdx.x;
    float2 v = *(const float2*)&Wf[2 * i];
    uint2 s = splitW(v.x, v.y);
    g_wfh[i] = s.x;
    g_wfl[i] = s.y;
}

// ---------------------------------------------------------------------------
// Kernel 2: attention. Q planes in smem, all fragments via ldmatrix.x4.
// smem words: QH 0 (256x36), QL 9216, KV double buffer at 18432:
//   each buffer [KH|KL|VH|VL] x (64x36), buffer stride 9216 words.
// ---------------------------------------------------------------------------
#define AQH_W 0
#define AQL_W 9216
#define AKV_W 18432
#define KVW   2304
#define ABUFW 9216
#define ATT_SMEM ((AKV_W + 2 * ABUFW) * 4)   // 147,456 B

__global__ __launch_bounds__(256, 1) void attn_mma(const int* __restrict__ mask)
{
    extern __shared__ uint32_t as_[];
    const uint32_t sb = smem_u32(as_);
    const int t = threadIdx.x, lane = t & 31, wid = t >> 5;
    const int lr = lane >> 2, lc = lane & 3;
    const int wm = wid * 32;
    const int roff = (lane & 7) + ((lane >> 3) & 1) * 8;   // ldmatrix row
    const int kwo  = (lane >> 4) * 4;                      // ldmatrix k-chunk
    const int w = blockIdx.x, h = blockIdx.y, nb = blockIdx.z;
    const size_t qbase = (size_t)nb * LSEQ + (size_t)w * WIN;

    // ---- group 0: Q planes -> smem ----
    for (int i = t; i < 2048; i += 256) {
        const int r = i >> 3, fc = i & 7;
        const size_t src = (qbase + r) * 512 + h * 32 + fc * 4;
        const uint32_t dw = (uint32_t)(r * 36 + fc * 4) * 4u;
        cp_async16(sb + (AQH_W << 2) + dw, &g_qh[src]);
        cp_async16(sb + (AQL_W << 2) + dw, &g_ql[src]);
    }
    CP_COMMIT();

    bool qv[2][2];
    #pragma unroll
    for (int mt = 0; mt < 2; mt++) {
        qv[mt][0] = mask[qbase + wm + mt * 16 + lr] != 0;
        qv[mt][1] = mask[qbase + wm + mt * 16 + lr + 8] != 0;
    }

    float m_[2][2], l_[2][2];
    #pragma unroll
    for (int mt = 0; mt < 2; mt++) {
        m_[mt][0] = -INFINITY; m_[mt][1] = -INFINITY;
        l_[mt][0] = 0.f;       l_[mt][1] = 0.f;
    }
    float cO[2][8][4];
    #pragma unroll
    for (int mt = 0; mt < 2; mt++)
        #pragma unroll
        for (int nf = 0; nf < 8; nf++)
            #pragma unroll
            for (int u = 0; u < 4; u++) cO[mt][nf][u] = 0.f;

    auto issue = [&](int c) {
        const uint32_t d0 = sb + (uint32_t)(AKV_W + (c & 1) * ABUFW) * 4u;
        for (int i = t; i < 512; i += 256) {          // K planes
            const int r = i >> 3, fc = i & 7;
            const int tok = w * WIN + c * 64 + r - OV;
            const uint32_t ok = ((unsigned)tok < (unsigned)LSEQ) ? 16u : 0u;
            const int tokc = ok ? tok : 0;
            const size_t src = (size_t)((size_t)nb * LSEQ + tokc) * 512 + h * 32 + fc * 4;
            const uint32_t dw = (uint32_t)(r * 36 + fc * 4) * 4u;
            cp_async16z(d0 + dw,            &g_kh[src], ok);
            cp_async16z(d0 + KVW * 4u + dw, &g_kl[src], ok);
        }
        for (int i = t; i < 512; i += 256) {          // V planes (transposed)
            const int e = i >> 3, fc = i & 7;
            const int tp0 = w * (WIN / 2) + c * 32 - OV / 2 + fc * 4;
            const uint32_t ok = ((unsigned)tp0 < (unsigned)(LSEQ / 2)) ? 16u : 0u;
            const int tpc = ok ? tp0 : 0;
            const size_t src = ((size_t)(nb * NH + h) * 64 + e) * 2048 + tpc;
            const uint32_t dw = (uint32_t)(e * 36 + fc * 4) * 4u;
            cp_async16z(d0 + 2u * KVW * 4u + dw, &g_vth[src], ok);
            cp_async16z(d0 + 3u * KVW * 4u + dw, &g_vtl[src], ok);
        }
        CP_COMMIT();
    };

    issue(0);

    for (int c = 0; c < 5; c++) {
        __syncthreads();
        if (c < 4) { issue(c + 1); CP_WAIT(1); } else { CP_WAIT(0); }
        __syncthreads();

        const uint32_t kvb = (uint32_t)(AKV_W + (c & 1) * ABUFW);

        // ---- S = Q K^T (3 passes), fragments via ldmatrix ----
        float cS[2][8][4];
        #pragma unroll
        for (int mt = 0; mt < 2; mt++)
            #pragma unroll
            for (int nf = 0; nf < 8; nf++)
                #pragma unroll
                for (int u = 0; u < 4; u++) cS[mt][nf][u] = 0.f;

        #pragma unroll
        for (int pass = 0; pass < 3; pass++) {
            const uint32_t qb = (pass == 1) ? AQL_W : AQH_W;
            const uint32_t kp = kvb + ((pass == 2) ? KVW : 0);
            #pragma unroll
            for (int kt = 0; kt < 4; kt++) {
                uint32_t a[2][4];
                #pragma unroll
                for (int mt = 0; mt < 2; mt++) {
                    const uint32_t ad = sb + ((qb + (wm + mt * 16 + roff) * 36
                                               + kt * 8 + kwo) << 2);
                    LDM_X4(a[mt][0], a[mt][1], a[mt][2], a[mt][3], ad);
                }
                #pragma unroll
                for (int p = 0; p < 4; p++) {
                    uint32_t b0e, b0o, b1e, b1o;
                    const uint32_t bd = sb + ((kp + (p * 16 + roff) * 36
                                               + kt * 8 + kwo) << 2);
                    LDM_X4(b0e, b0o, b1e, b1o, bd);
                    MMA_BF16(cS[0][2 * p],     a[0][0], a[0][1], a[0][2], a[0][3], b0e, b1e);
                    MMA_BF16(cS[0][2 * p + 1], a[0][0], a[0][1], a[0][2], a[0][3], b0o, b1o);
                    MMA_BF16(cS[1][2 * p],     a[1][0], a[1][1], a[1][2], a[1][3], b0e, b1e);
                    MMA_BF16(cS[1][2 * p + 1], a[1][0], a[1][1], a[1][2], a[1][3], b0o, b1o);
                }
            }
        }

        // ---- register softmax ----
        const int cbase = w * WIN + c * 64 - OV;
        const bool vlo = (cbase >= 0);
        const bool vhi = (cbase + 63 < LSEQ);

        #pragma unroll
        for (int mt = 0; mt < 2; mt++) {
            float mx0 = -INFINITY, mx1 = -INFINITY;
            #pragma unroll
            for (int nf = 0; nf < 8; nf++) {
                const bool kv = (nf < 4) ? vlo : vhi;
                float x0 = cS[mt][nf][0] * 0.125f, x1 = cS[mt][nf][1] * 0.125f;
                float x2 = cS[mt][nf][2] * 0.125f, x3 = cS[mt][nf][3] * 0.125f;
                if (!qv[mt][0]) { x0 = -1.25e9f; x1 = -1.25e9f; }
                if (!qv[mt][1]) { x2 = -1.25e9f; x3 = -1.25e9f; }
                if (!kv) { x0 = -INFINITY; x1 = -INFINITY; x2 = -INFINITY; x3 = -INFINITY; }
                cS[mt][nf][0] = x0; cS[mt][nf][1] = x1;
                cS[mt][nf][2] = x2; cS[mt][nf][3] = x3;
                mx0 = fmaxf(mx0, fmaxf(x0, x1));
                mx1 = fmaxf(mx1, fmaxf(x2, x3));
            }
            mx0 = fmaxf(mx0, __shfl_xor_sync(0xffffffffu, mx0, 1));
            mx0 = fmaxf(mx0, __shfl_xor_sync(0xffffffffu, mx0, 2));
            mx1 = fmaxf(mx1, __shfl_xor_sync(0xffffffffu, mx1, 1));
            mx1 = fmaxf(mx1, __shfl_xor_sync(0xffffffffu, mx1, 2));

            const float mn0 = fmaxf(m_[mt][0], mx0);
            const float mn1 = fmaxf(m_[mt][1], mx1);
            const float cr0 = __expf(m_[mt][0] - mn0);
            const float cr1 = __expf(m_[mt][1] - mn1);
            m_[mt][0] = mn0; m_[mt][1] = mn1;

            float ls0 = 0.f, ls1 = 0.f;
            #pragma unroll
            for (int nf = 0; nf < 8; nf++) {
                const float p0 = __expf(cS[mt][nf][0] - mn0);
                const float p1 = __expf(cS[mt][nf][1] - mn0);
                const float p2 = __expf(cS[mt][nf][2] - mn1);
                const float p3 = __expf(cS[mt][nf][3] - mn1);
                cS[mt][nf][0] = p0; cS[mt][nf][1] = p1;
                cS[mt][nf][2] = p2; cS[mt][nf][3] = p3;
                ls0 += p0 + p1; ls1 += p2 + p3;
            }
            ls0 += __shfl_xor_sync(0xffffffffu, ls0, 1);
            ls0 += __shfl_xor_sync(0xffffffffu, ls0, 2);
            ls1 += __shfl_xor_sync(0xffffffffu, ls1, 1);
            ls1 += __shfl_xor_sync(0xffffffffu, ls1, 2);
            l_[mt][0] = l_[mt][0] * cr0 + ls0;
            l_[mt][1] = l_[mt][1] * cr1 + ls1;

            #pragma unroll
            for (int nf = 0; nf < 8; nf++) {
                cO[mt][nf][0] *= cr0; cO[mt][nf][1] *= cr0;
                cO[mt][nf][2] *= cr1; cO[mt][nf][3] *= cr1;
            }
        }

        // ---- O += P V (3 terms), V fragments via ldmatrix ----
        #pragma unroll
        for (int kt = 0; kt < 4; kt++) {
            uint32_t phi[2][4], plo[2][4];
            #pragma unroll
            for (int mt = 0; mt < 2; mt++) {
                uint2 s0 = splitW(cS[mt][2 * kt][0],     cS[mt][2 * kt][1]);
                uint2 s1 = splitW(cS[mt][2 * kt][2],     cS[mt][2 * kt][3]);
                uint2 s2 = splitW(cS[mt][2 * kt + 1][0], cS[mt][2 * kt + 1][1]);
                uint2 s3 = splitW(cS[mt][2 * kt + 1][2], cS[mt][2 * kt + 1][3]);
                phi[mt][0] = s0.x; plo[mt][0] = s0.y;
                phi[mt][1] = s1.x; plo[mt][1] = s1.y;
                phi[mt][2] = s2.x; plo[mt][2] = s2.y;
                phi[mt][3] = s3.x; plo[mt][3] = s3.y;
            }
            #pragma unroll
            for (int p = 0; p < 4; p++) {
                uint32_t h0e, h0o, h1e, h1o, l0e, l0o, l1e, l1o;
                const uint32_t vh = sb + ((kvb + 2 * KVW + (p * 16 + roff) * 36
                                           + kt * 8 + kwo) << 2);
                LDM_X4(h0e, h0o, h1e, h1o, vh);
                LDM_X4(l0e, l0o, l1e, l1o, vh + KVW * 4u);
                #pragma unroll
                for (int mt = 0; mt < 2; mt++) {
                    MMA_BF16(cO[mt][2 * p],     phi[mt][0], phi[mt][1], phi[mt][2], phi[mt][3], h0e, h1e);
                    MMA_BF16(cO[mt][2 * p],     plo[mt][0], plo[mt][1], plo[mt][2], plo[mt][3], h0e, h1e);
                    MMA_BF16(cO[mt][2 * p],     phi[mt][0], phi[mt][1], phi[mt][2], phi[mt][3], l0e, l1e);
                    MMA_BF16(cO[mt][2 * p + 1], phi[mt][0], phi[mt][1], phi[mt][2], phi[mt][3], h0o, h1o);
                    MMA_BF16(cO[mt][2 * p + 1], plo[mt][0], plo[mt][1], plo[mt][2], plo[mt][3], h0o, h1o);
                    MMA_BF16(cO[mt][2 * p + 1], phi[mt][0], phi[mt][1], phi[mt][2], phi[mt][3], l0o, l1o);
                }
            }
        }
    }

    // ---- epilogue ----
    #pragma unroll
    for (int mt = 0; mt < 2; mt++) {
        const float i0 = (l_[mt][0] > 0.f) ? (1.f / l_[mt][0]) : 0.f;
        const float i1 = (l_[mt][1] > 0.f) ? (1.f / l_[mt][1]) : 0.f;
        const size_t rw = (qbase + wm + mt * 16 + lr) * 512 + h * 32;
        #pragma unroll
        for (int nf = 0; nf < 8; nf++) {
            const size_t wrd = rw + nf * 4 + lc;
            uint2 s0 = splitW(cO[mt][nf][0] * i0, cO[mt][nf][1] * i0);
            uint2 s1 = splitW(cO[mt][nf][2] * i1, cO[mt][nf][3] * i1);
            g_ahp[wrd] = s0.x;              g_alp[wrd] = s0.y;
            g_ahp[wrd + 8 * 512] = s1.x;    g_alp[wrd + 8 * 512] = s1.y;
        }
    }
}

// ---------------------------------------------------------------------------
// Kernel 3: output projection, bf16x3, fragments via ldmatrix.
// ---------------------------------------------------------------------------
#define GKT       32
#define PL_W      2048
#define STG_W     (4 * PL_W)
#define SMEM_GEMM (3 * STG_W * 4)
#define SWZ(r)    ((((r) >> 1) & 3) << 2)

__global__ __launch_bounds__(256, 2) void out_gemm_bf16(
    const float* __restrict__ bf, float* __restrict__ out)
{
    extern __shared__ uint32_t su[];
    const uint32_t sb = smem_u32(su);
    const int tid  = threadIdx.x, lane = tid & 31, wid = tid >> 5;
    const int wm   = (wid & 1) * 64;
    const int wn   = (wid >> 1) * 32;
    const size_t m0 = (size_t)blockIdx.y * 128;
    const int e0   = blockIdx.x * 128;
    const int lr = lane >> 2, lc = lane & 3;
    const int roff = (lane & 7) + ((lane >> 3) & 1) * 8;
    const int kwo  = (lane >> 4) * 4;
    const int frow = tid >> 2, fc = tid & 3;

    float c[4][4][4];
    #pragma unroll
    for (int i = 0; i < 4; i++)
        #pragma unroll
        for (int j = 0; j < 4; j++)
            #pragma unroll
            for (int u = 0; u < 4; u++) c[i][j][u] = 0.f;

    const char* pAh = (const char*)g_ahp;
    const char* pAl = (const char*)g_alp;
    const char* pBh = (const char*)g_wfh;
    const char* pBl = (const char*)g_wfl;

    auto issue = [&](int s) {
        const uint32_t stw = (uint32_t)(s % 3) * STG_W;
        #pragma unroll
        for (int rt = 0; rt < 2; rt++) {
            const int row = frow + rt * 64;
            const uint32_t offw = (uint32_t)row * 16u + ((uint32_t)(fc * 4) ^ SWZ(row));
            const size_t gA = (size_t)(m0 + row) * 2048 + (size_t)s * 64 + fc * 16;
            const size_t gB = (size_t)(e0 + row) * 2048 + (size_t)s * 64 + fc * 16;
            cp_async16(sb + (stw + offw) * 4,            pAh + gA);
            cp_async16(sb + (stw + PL_W + offw) * 4,     pAl + gA);
            cp_async16(sb + (stw + 2 * PL_W + offw) * 4, pBh + gB);
            cp_async16(sb + (stw + 3 * PL_W + offw) * 4, pBl + gB);
        }
        CP_COMMIT();
    };

    issue(0);
    issue(1);

    for (int t = 0; t < GKT; t++) {
        if (t < GKT - 1) { CP_WAIT(1); } else { CP_WAIT(0); }
        __syncthreads();
        if (t + 2 < GKT) issue(t + 2);

        const uint32_t stw = (uint32_t)(t % 3) * STG_W;
        #pragma unroll
        for (int ks = 0; ks < 2; ks++) {
            const int wl = ks * 8;
            uint32_t ah[4][4], al[4][4];
            #pragma unroll
            for (int mt = 0; mt < 4; mt++) {
                const int row = wm + mt * 16 + roff;
                const uint32_t ad = sb + ((stw + (uint32_t)row * 16u +
                                  ((uint32_t)(wl + kwo) ^ SWZ(row))) << 2);
                LDM_X4(ah[mt][0], ah[mt][1], ah[mt][2], ah[mt][3], ad);
                LDM_X4(al[mt][0], al[mt][1], al[mt][2], al[mt][3], ad + PL_W * 4u);
            }
            #pragma unroll
            for (int p = 0; p < 2; p++) {
                const int n = wn + p * 16 + roff;
                const uint32_t bd = sb + ((stw + 2 * PL_W + (uint32_t)n * 16u +
                                  ((uint32_t)(wl + kwo) ^ SWZ(n))) << 2);
                uint32_t h0e, h0o, h1e, h1o, l0e, l0o, l1e, l1o;
                LDM_X4(h0e, h0o, h1e, h1o, bd);
                LDM_X4(l0e, l0o, l1e, l1o, bd + PL_W * 4u);
                #pragma unroll
                for (int mt = 0; mt < 4; mt++) {
                    MMA_BF16(c[mt][2 * p],     ah[mt][0], ah[mt][1], ah[mt][2], ah[mt][3], h0e, h1e);
                    MMA_BF16(c[mt][2 * p],     al[mt][0], al[mt][1], al[mt][2], al[mt][3], h0e, h1e);
                    MMA_BF16(c[mt][2 * p],     ah[mt][0], ah[mt][1], ah[mt][2], ah[mt][3], l0e, l1e);
                    MMA_BF16(c[mt][2 * p + 1], ah[mt][0], ah[mt][1], ah[mt][2], ah[mt][3], h0o, h1o);
                    MMA_BF16(c[mt][2 * p + 1], al[mt][0], al[mt][1], al[mt][2], al[mt][3], h0o, h1o);
                    MMA_BF16(c[mt][2 * p + 1], ah[mt][0], ah[mt][1], ah[mt][2], ah[mt][3], l0o, l1o);
                }
            }
        }
        __syncthreads();
    }

    #pragma unroll
    for (int mt = 0; mt < 4; mt++) {
        #pragma unroll
        for (int nf = 0; nf < 4; nf++) {
            const int mr  = (int)m0 + wm + mt * 16 + lr;
            const int col = e0 + wn + nf * 8 + lc * 2;
            const float b0 = bf[col], b1 = bf[col + 1];
            *(float2*)&out[(size_t)mr * EMB + col] =
                make_float2(c[mt][nf][0] + b0, c[mt][nf][1] + b1);
            *(float2*)&out[(size_t)(mr + 8) * EMB + col] =
                make_float2(c[mt][nf][2] + b0, c[mt][nf][3] + b1);
        }
    }
}

// ---------------------------------------------------------------------------
extern "C" void kernel_launch(void* const* d_in, const int* in_sizes, int n_in,
                              void* d_out, int out_size)
{
    const float* vals = (const float*)d_in[0];
    const float* keys = (const float*)d_in[1];
    const float* qrs  = (const float*)d_in[2];
    const int*   mask = (const int*)d_in[3];
    const float* Wv   = (const float*)d_in[4];
    const float* Wk   = (const float*)d_in[5];
    const float* Wq   = (const float*)d_in[6];
    const float* Wf   = (const float*)d_in[7];
    const float* bf   = (const float*)d_in[8];
    float* out = (float*)d_out;

    cudaFuncSetAttribute(proj_mma,
                         cudaFuncAttributeMaxDynamicSharedMemorySize, PJ_SMEM);
    cudaFuncSetAttribute(attn_mma,
                         cudaFuncAttributeMaxDynamicSharedMemorySize, ATT_SMEM);
    cudaFuncSetAttribute(out_gemm_bf16,
                         cudaFuncAttributeMaxDynamicSharedMemorySize, SMEM_GEMM);

    proj_mma<<<dim3(NB * LSEQ / 128, NH, 3), 256, PJ_SMEM>>>(vals, keys, qrs, Wv, Wk, Wq);
    wf_split_kernel<<<EMB * EMB / 512, 256>>>(Wf);
    attn_mma<<<dim3(NWIN, NH, NB), 256, ATT_SMEM>>>(mask);
    out_gemm_bf16<<<dim3(EMB / 128, NB * LSEQ / 128), 256, SMEM_GEMM>>>(bf, out);
}

// round 16
// speedup vs baseline: 1.9472x; 1.0392x over previous
#include <cuda_runtime.h>
#include <math.h>
#include <stdint.h>

#define NB   4
#define LSEQ 4096
#define EMB  1024
#define NH   16
#define HD   64
#define WIN  256
#define OV   32
#define NWIN 16

// ---- device scratch (packed bf16x2 plane words) ----
__device__ uint32_t g_qh[(size_t)NB * LSEQ * EMB / 2];
__device__ uint32_t g_ql[(size_t)NB * LSEQ * EMB / 2];
__device__ uint32_t g_kh[(size_t)NB * LSEQ * EMB / 2];
__device__ uint32_t g_kl[(size_t)NB * LSEQ * EMB / 2];
// V transposed planes: idx = ((nb*NH+h)*64 + e)*2048 + token_pair
__device__ uint32_t g_vth[(size_t)NB * NH * HD * (LSEQ / 2)];
__device__ uint32_t g_vtl[(size_t)NB * NH * HD * (LSEQ / 2)];
// attention output planes (word = row*512 + col/2)
__device__ uint32_t g_ahp[(size_t)NB * LSEQ * EMB / 2];
__device__ uint32_t g_alp[(size_t)NB * LSEQ * EMB / 2];
// Wf planes
__device__ uint32_t g_wfh[(size_t)EMB * EMB / 2];
__device__ uint32_t g_wfl[(size_t)EMB * EMB / 2];
// Wv/Wk/Wq planes (64x64 each, shared across heads)
__device__ uint32_t g_wsph[3 * 2048];
__device__ uint32_t g_wspl[3 * 2048];

// ===========================================================================
__device__ __forceinline__ uint32_t smem_u32(const void* p) {
    uint32_t a;
    asm("{ .reg .u64 t; cvta.to.shared.u64 t, %1; cvt.u32.u64 %0, t; }"
        : "=r"(a) : "l"(p));
    return a;
}
__device__ __forceinline__ void cp_async16(uint32_t s, const void* g) {
    asm volatile("cp.async.cg.shared.global [%0], [%1], 16;" :: "r"(s), "l"(g));
}
__device__ __forceinline__ void cp_async16z(uint32_t s, const void* g, uint32_t sz) {
    asm volatile("cp.async.cg.shared.global [%0], [%1], 16, %2;"
                 :: "r"(s), "l"(g), "r"(sz));
}
#define CP_COMMIT() asm volatile("cp.async.commit_group;" ::: "memory")
#define CP_WAIT(N)  asm volatile("cp.async.wait_group %0;" :: "n"(N) : "memory")

__device__ __forceinline__ uint32_t bf16_rn_bits(float x) {
    uint32_t xi = __float_as_uint(x);
    return (xi + 0x7FFFu + ((xi >> 16) & 1u)) >> 16;
}
__device__ __forceinline__ uint2 splitW(float x, float y) {
    uint32_t xi = __float_as_uint(x), yi = __float_as_uint(y);
    float rx = x - __uint_as_float(xi & 0xFFFF0000u);
    float ry = y - __uint_as_float(yi & 0xFFFF0000u);
    return make_uint2((xi >> 16) | ((yi >> 16) << 16),
                      bf16_rn_bits(rx) | (bf16_rn_bits(ry) << 16));
}

#define MMA_BF16(c, a0, a1, a2, a3, b0, b1) \
    asm volatile("mma.sync.aligned.m16n8k16.row.col.f32.bf16.bf16.f32 " \
                 "{%0,%1,%2,%3}, {%4,%5,%6,%7}, {%8,%9}, {%0,%1,%2,%3};" \
                 : "+f"((c)[0]), "+f"((c)[1]), "+f"((c)[2]), "+f"((c)[3]) \
                 : "r"(a0), "r"(a1), "r"(a2), "r"(a3), "r"(b0), "r"(b1))

#define LDM_X4(r0, r1, r2, r3, addr) \
    asm volatile("ldmatrix.sync.aligned.m8n8.x4.shared.b16 {%0,%1,%2,%3}, [%4];" \
                 : "=r"(r0), "=r"(r1), "=r"(r2), "=r"(r3) : "r"(addr))

// ---------------------------------------------------------------------------
// Kernel 0: split Wv/Wk/Wq into bf16 planes once (shared across heads).
// ---------------------------------------------------------------------------
__global__ __launch_bounds__(256) void w3_split(
    const float* __restrict__ Wv, const float* __restrict__ Wk,
    const float* __restrict__ Wq)
{
    const float* W = (blockIdx.x == 0) ? Wv : ((blockIdx.x == 1) ? Wk : Wq);
    for (int i = threadIdx.x; i < 2048; i += 256) {
        float2 v = *(const float2*)&W[2 * i];
        uint2 s = splitW(v.x, v.y);
        g_wsph[blockIdx.x * 2048 + i] = s.x;
        g_wspl[blockIdx.x * 2048 + i] = s.y;
    }
}

// ---------------------------------------------------------------------------
// Kernel 1b: split Wf into bf16 planes.
// ---------------------------------------------------------------------------
__global__ __launch_bounds__(256) void wf_split_kernel(const float* __restrict__ Wf)
{
    const int i = blockIdx.x * 256 + threadIdx.x;
    float2 v = *(const float2*)&Wf[2 * i];
    uint2 s = splitW(v.x, v.y);
    g_wfh[i] = s.x;
    g_wfl[i] = s.y;
}

// ---------------------------------------------------------------------------
// Kernel 1: q/k/v projection via bf16x3 mma. W planes via cp.async;
// q/k epilogue staged through smem for coalesced uint4 plane writes.
// ---------------------------------------------------------------------------
#define PJW 36
#define PJ_XH 0
#define PJ_XL 4608
#define PJ_WH 9216
#define PJ_WL 11520
#define PJ_SMEM (13824 * 4)

__global__ __launch_bounds__(256) void proj_mma(
    const float* __restrict__ vals, const float* __restrict__ keys,
    const float* __restrict__ qrs)
{
    extern __shared__ uint32_t ps[];
    const uint32_t sbp = smem_u32(ps);
    const int t = threadIdx.x, lane = t & 31, wid = t >> 5;
    const int lr = lane >> 2, lc = lane & 3;
    const int h = blockIdx.y, which = blockIdx.z;
    const size_t r0 = (size_t)blockIdx.x * 128;

    const float* X = (which == 0) ? vals : ((which == 1) ? keys : qrs);

    // W planes via cp.async (pre-split, head-shared)
    for (int i = t; i < 512; i += 256) {
        const int r = i >> 3, fc = i & 7;
        const uint32_t dw = (uint32_t)(r * PJW + fc * 4) * 4u;
        cp_async16(sbp + PJ_WH * 4u + dw, &g_wsph[which * 2048 + r * 32 + fc * 4]);
        cp_async16(sbp + PJ_WL * 4u + dw, &g_wspl[which * 2048 + r * 32 + fc * 4]);
    }
    CP_COMMIT();

    // X tile load + split
    for (int i = t; i < 2048; i += 256) {
        int r = i >> 4, g = i & 15;
        float4 v = *(const float4*)&X[(r0 + r) * EMB + h * HD + g * 4];
        uint2 s01 = splitW(v.x, v.y), s23 = splitW(v.z, v.w);
        ps[PJ_XH + r * PJW + g * 2]     = s01.x;
        ps[PJ_XH + r * PJW + g * 2 + 1] = s23.x;
        ps[PJ_XL + r * PJW + g * 2]     = s01.y;
        ps[PJ_XL + r * PJW + g * 2 + 1] = s23.y;
    }
    CP_WAIT(0);
    __syncthreads();

    const int am = wid * 16;
    float c[8][4];
    #pragma unroll
    for (int nf = 0; nf < 8; nf++)
        #pragma unroll
        for (int u = 0; u < 4; u++) c[nf][u] = 0.f;

    #pragma unroll
    for (int pass = 0; pass < 3; pass++) {
        const int ab = (pass == 1) ? PJ_XL : PJ_XH;
        const int bb = (pass == 2) ? PJ_WL : PJ_WH;
        #pragma unroll
        for (int kt = 0; kt < 4; kt++) {
            const int abase = ab + (am + lr) * PJW + kt * 8 + lc;
            uint32_t a0 = ps[abase],     a1 = ps[abase + 8 * PJW];
            uint32_t a2 = ps[abase + 4], a3 = ps[abase + 8 * PJW + 4];
            #pragma unroll
            for (int nf = 0; nf < 8; nf++) {
                const int bbase = bb + (nf * 8 + lr) * PJW + kt * 8 + lc;
                MMA_BF16(c[nf], a0, a1, a2, a3, ps[bbase], ps[bbase + 4]);
            }
        }
    }

    if (which >= 1) {
        uint32_t* ph = (which == 2) ? g_qh : g_kh;
        uint32_t* pl = (which == 2) ? g_ql : g_kl;
        // stage split planes in smem (stride 36, conflict-free)
        __syncthreads();
        #pragma unroll
        for (int nf = 0; nf < 8; nf++) {
            uint2 s0 = splitW(c[nf][0], c[nf][1]);
            uint2 s1 = splitW(c[nf][2], c[nf][3]);
            const int row0 = am + lr, row1 = row0 + 8;
            ps[row0 * 36 + nf * 4 + lc]        = s0.x;
            ps[4608 + row0 * 36 + nf * 4 + lc] = s0.y;
            ps[row1 * 36 + nf * 4 + lc]        = s1.x;
            ps[4608 + row1 * 36 + nf * 4 + lc] = s1.y;
        }
        __syncthreads();
        // coalesced uint4 writes
        #pragma unroll
        for (int it = 0; it < 4; it++) {
            const int u = it * 256 + t;
            const int row = u >> 3, w4 = u & 7;
            *(uint4*)&ph[(r0 + row) * 512 + h * 32 + w4 * 4] =
                *(uint4*)&ps[row * 36 + w4 * 4];
            *(uint4*)&pl[(r0 + row) * 512 + h * 32 + w4 * 4] =
                *(uint4*)&ps[4608 + row * 36 + w4 * 4];
        }
    } else {
        // V: transpose via smem, write transposed planes (already coalesced)
        __syncthreads();
        float* sv = (float*)ps;
        #pragma unroll
        for (int nf = 0; nf < 8; nf++) {
            const int col = nf * 8 + 2 * lc;
            sv[col * 132 + am + lr]           = c[nf][0];
            sv[(col + 1) * 132 + am + lr]     = c[nf][1];
            sv[col * 132 + am + lr + 8]       = c[nf][2];
            sv[(col + 1) * 132 + am + lr + 8] = c[nf][3];
        }
        __syncthreads();
        const int nb = (int)(r0 / LSEQ);
        const size_t base = ((size_t)(nb * NH + h) * 64) * 2048 + (r0 % LSEQ) / 2;
        const int tp = t & 63, e0 = t >> 6;
        #pragma unroll
        for (int it = 0; it < 16; it++) {
            const int e = it * 4 + e0;
            float2 v = *(const float2*)&sv[e * 132 + 2 * tp];
            uint2 s = splitW(v.x, v.y);
            g_vth[base + (size_t)e * 2048 + tp] = s.x;
            g_vtl[base + (size_t)e * 2048 + tp] = s.y;
        }
    }
}

// ---------------------------------------------------------------------------
// Kernel 2: attention, 128 queries/block (2 CTAs/SM), ldmatrix fragments,
// register softmax, staged coalesced epilogue.
// smem words: QH 0 (128x36), QL 4608, KV double buffer at 9216
//   (each buffer [KH|KL|VH|VL] x (64x36) = 9216 words). Total 110,592 B.
// ---------------------------------------------------------------------------
#define AQH_W 0
#define AQL_W 4608
#define AKV_W 9216
#define KVW   2304
#define ABUFW 9216
#define AST_H AKV_W
#define AST_L (AKV_W + 4608)
#define ATT_SMEM ((AKV_W + 2 * ABUFW) * 4)   // 110,592 B

__global__ __launch_bounds__(256, 2) void attn_mma(const int* __restrict__ mask)
{
    extern __shared__ uint32_t as_[];
    const uint32_t sb = smem_u32(as_);
    const int t = threadIdx.x, lane = t & 31, wid = t >> 5;
    const int lr = lane >> 2, lc = lane & 3;
    const int wm = wid * 16;
    const int roff = (lane & 7) + ((lane >> 3) & 1) * 8;
    const int kwo  = (lane >> 4) * 4;
    const int w2 = blockIdx.x, h = blockIdx.y, nb = blockIdx.z;
    const int w = w2 >> 1;
    const size_t qbase = (size_t)nb * LSEQ + (size_t)w * WIN + (w2 & 1) * 128;

    // Q planes -> smem
    for (int i = t; i < 1024; i += 256) {
        const int r = i >> 3, fc = i & 7;
        const size_t src = (qbase + r) * 512 + h * 32 + fc * 4;
        const uint32_t dw = (uint32_t)(r * 36 + fc * 4) * 4u;
        cp_async16(sb + dw,               &g_qh[src]);
        cp_async16(sb + AQL_W * 4u + dw,  &g_ql[src]);
    }
    CP_COMMIT();

    const bool qv0 = mask[qbase + wm + lr] != 0;
    const bool qv1 = mask[qbase + wm + lr + 8] != 0;

    float m0 = -INFINITY, m1 = -INFINITY, l0 = 0.f, l1 = 0.f;
    float cO[8][4];
    #pragma unroll
    for (int nf = 0; nf < 8; nf++)
        #pragma unroll
        for (int u = 0; u < 4; u++) cO[nf][u] = 0.f;

    auto issue = [&](int c) {
        const uint32_t d0 = sb + (uint32_t)(AKV_W + (c & 1) * ABUFW) * 4u;
        for (int i = t; i < 512; i += 256) {          // K planes
            const int r = i >> 3, fc = i & 7;
            const int tok = w * WIN + c * 64 + r - OV;
            const uint32_t ok = ((unsigned)tok < (unsigned)LSEQ) ? 16u : 0u;
            const int tokc = ok ? tok : 0;
            const size_t src = (size_t)((size_t)nb * LSEQ + tokc) * 512 + h * 32 + fc * 4;
            const uint32_t dw = (uint32_t)(r * 36 + fc * 4) * 4u;
            cp_async16z(d0 + dw,            &g_kh[src], ok);
            cp_async16z(d0 + KVW * 4u + dw, &g_kl[src], ok);
        }
        for (int i = t; i < 512; i += 256) {          // V planes (transposed)
            const int e = i >> 3, fc = i & 7;
            const int tp0 = w * (WIN / 2) + c * 32 - OV / 2 + fc * 4;
            const uint32_t ok = ((unsigned)tp0 < (unsigned)(LSEQ / 2)) ? 16u : 0u;
            const int tpc = ok ? tp0 : 0;
            const size_t src = ((size_t)(nb * NH + h) * 64 + e) * 2048 + tpc;
            const uint32_t dw = (uint32_t)(e * 36 + fc * 4) * 4u;
            cp_async16z(d0 + 2u * KVW * 4u + dw, &g_vth[src], ok);
            cp_async16z(d0 + 3u * KVW * 4u + dw, &g_vtl[src], ok);
        }
        CP_COMMIT();
    };

    issue(0);

    for (int c = 0; c < 5; c++) {
        __syncthreads();
        if (c < 4) { issue(c + 1); CP_WAIT(1); } else { CP_WAIT(0); }
        __syncthreads();

        const uint32_t kvb = (uint32_t)(AKV_W + (c & 1) * ABUFW);

        // ---- S = Q K^T (3 passes) ----
        float cS[8][4];
        #pragma unroll
        for (int nf = 0; nf < 8; nf++)
            #pragma unroll
            for (int u = 0; u < 4; u++) cS[nf][u] = 0.f;

        #pragma unroll
        for (int pass = 0; pass < 3; pass++) {
            const uint32_t qb = (pass == 1) ? AQL_W : AQH_W;
            const uint32_t kp = kvb + ((pass == 2) ? KVW : 0);
            #pragma unroll
            for (int kt = 0; kt < 4; kt++) {
                uint32_t a0, a1, a2, a3;
                const uint32_t ad = sb + ((qb + (wm + roff) * 36 + kt * 8 + kwo) << 2);
                LDM_X4(a0, a1, a2, a3, ad);
                #pragma unroll
                for (int p = 0; p < 4; p++) {
                    uint32_t b0e, b0o, b1e, b1o;
                    const uint32_t bd = sb + ((kp + (p * 16 + roff) * 36
                                               + kt * 8 + kwo) << 2);
                    LDM_X4(b0e, b0o, b1e, b1o, bd);
                    MMA_BF16(cS[2 * p],     a0, a1, a2, a3, b0e, b1e);
                    MMA_BF16(cS[2 * p + 1], a0, a1, a2, a3, b0o, b1o);
                }
            }
        }

        // ---- register softmax ----
        const int cbase = w * WIN + c * 64 - OV;
        const bool vlo = (cbase >= 0);
        const bool vhi = (cbase + 63 < LSEQ);

        float mx0 = -INFINITY, mx1 = -INFINITY;
        #pragma unroll
        for (int nf = 0; nf < 8; nf++) {
            const bool kv = (nf < 4) ? vlo : vhi;
            float x0 = cS[nf][0] * 0.125f, x1 = cS[nf][1] * 0.125f;
            float x2 = cS[nf][2] * 0.125f, x3 = cS[nf][3] * 0.125f;
            if (!qv0) { x0 = -1.25e9f; x1 = -1.25e9f; }
            if (!qv1) { x2 = -1.25e9f; x3 = -1.25e9f; }
            if (!kv) { x0 = -INFINITY; x1 = -INFINITY; x2 = -INFINITY; x3 = -INFINITY; }
            cS[nf][0] = x0; cS[nf][1] = x1;
            cS[nf][2] = x2; cS[nf][3] = x3;
            mx0 = fmaxf(mx0, fmaxf(x0, x1));
            mx1 = fmaxf(mx1, fmaxf(x2, x3));
        }
        mx0 = fmaxf(mx0, __shfl_xor_sync(0xffffffffu, mx0, 1));
        mx0 = fmaxf(mx0, __shfl_xor_sync(0xffffffffu, mx0, 2));
        mx1 = fmaxf(mx1, __shfl_xor_sync(0xffffffffu, mx1, 1));
        mx1 = fmaxf(mx1, __shfl_xor_sync(0xffffffffu, mx1, 2));

        const float mn0 = fmaxf(m0, mx0);
        const float mn1 = fmaxf(m1, mx1);
        const float cr0 = __expf(m0 - mn0);
        const float cr1 = __expf(m1 - mn1);
        m0 = mn0; m1 = mn1;

        float ls0 = 0.f, ls1 = 0.f;
        #pragma unroll
        for (int nf = 0; nf < 8; nf++) {
            const float p0 = __expf(cS[nf][0] - mn0);
            const float p1 = __expf(cS[nf][1] - mn0);
            const float p2 = __expf(cS[nf][2] - mn1);
            const float p3 = __expf(cS[nf][3] - mn1);
            cS[nf][0] = p0; cS[nf][1] = p1;
            cS[nf][2] = p2; cS[nf][3] = p3;
            ls0 += p0 + p1; ls1 += p2 + p3;
        }
        ls0 += __shfl_xor_sync(0xffffffffu, ls0, 1);
        ls0 += __shfl_xor_sync(0xffffffffu, ls0, 2);
        ls1 += __shfl_xor_sync(0xffffffffu, ls1, 1);
        ls1 += __shfl_xor_sync(0xffffffffu, ls1, 2);
        l0 = l0 * cr0 + ls0;
        l1 = l1 * cr1 + ls1;

        #pragma unroll
        for (int nf = 0; nf < 8; nf++) {
            cO[nf][0] *= cr0; cO[nf][1] *= cr0;
            cO[nf][2] *= cr1; cO[nf][3] *= cr1;
        }

        // ---- O += P V (3 terms) ----
        #pragma unroll
        for (int kt = 0; kt < 4; kt++) {
            uint2 s0 = splitW(cS[2 * kt][0],     cS[2 * kt][1]);
            uint2 s1 = splitW(cS[2 * kt][2],     cS[2 * kt][3]);
            uint2 s2 = splitW(cS[2 * kt + 1][0], cS[2 * kt + 1][1]);
            uint2 s3 = splitW(cS[2 * kt + 1][2], cS[2 * kt + 1][3]);
            const uint32_t ph0 = s0.x, ph1 = s1.x, ph2 = s2.x, ph3 = s3.x;
            const uint32_t pl0 = s0.y, pl1 = s1.y, pl2 = s2.y, pl3 = s3.y;
            #pragma unroll
            for (int p = 0; p < 4; p++) {
                uint32_t h0e, h0o, h1e, h1o, l0e, l0o, l1e, l1o;
                const uint32_t vh = sb + ((kvb + 2 * KVW + (p * 16 + roff) * 36
                                           + kt * 8 + kwo) << 2);
                LDM_X4(h0e, h0o, h1e, h1o, vh);
                LDM_X4(l0e, l0o, l1e, l1o, vh + KVW * 4u);
                MMA_BF16(cO[2 * p],     ph0, ph1, ph2, ph3, h0e, h1e);
                MMA_BF16(cO[2 * p],     pl0, pl1, pl2, pl3, h0e, h1e);
                MMA_BF16(cO[2 * p],     ph0, ph1, ph2, ph3, l0e, l1e);
                MMA_BF16(cO[2 * p + 1], ph0, ph1, ph2, ph3, h0o, h1o);
                MMA_BF16(cO[2 * p + 1], pl0, pl1, pl2, pl3, h0o, h1o);
                MMA_BF16(cO[2 * p + 1], ph0, ph1, ph2, ph3, l0o, l1o);
            }
        }
    }

    // ---- epilogue: 1/l, stage planes in smem, coalesced uint4 writes ----
    const float i0 = (l0 > 0.f) ? (1.f / l0) : 0.f;
    const float i1 = (l1 > 0.f) ? (1.f / l1) : 0.f;
    __syncthreads();
    #pragma unroll
    for (int nf = 0; nf < 8; nf++) {
        uint2 s0 = splitW(cO[nf][0] * i0, cO[nf][1] * i0);
        uint2 s1 = splitW(cO[nf][2] * i1, cO[nf][3] * i1);
        const int row0 = wm + lr, row1 = row0 + 8;
        as_[AST_H + row0 * 36 + nf * 4 + lc] = s0.x;
        as_[AST_L + row0 * 36 + nf * 4 + lc] = s0.y;
        as_[AST_H + row1 * 36 + nf * 4 + lc] = s1.x;
        as_[AST_L + row1 * 36 + nf * 4 + lc] = s1.y;
    }
    __syncthreads();
    #pragma unroll
    for (int it = 0; it < 4; it++) {
        const int u = it * 256 + t;
        const int row = u >> 3, w4 = u & 7;
        *(uint4*)&g_ahp[(qbase + row) * 512 + h * 32 + w4 * 4] =
            *(uint4*)&as_[AST_H + row * 36 + w4 * 4];
        *(uint4*)&g_alp[(qbase + row) * 512 + h * 32 + w4 * 4] =
            *(uint4*)&as_[AST_L + row * 36 + w4 * 4];
    }
}

// ---------------------------------------------------------------------------
// Kernel 3: output projection, bf16x3, ldmatrix fragments (unchanged).
// ---------------------------------------------------------------------------
#define GKT       32
#define PL_W      2048
#define STG_W     (4 * PL_W)
#define SMEM_GEMM (3 * STG_W * 4)
#define SWZ(r)    ((((r) >> 1) & 3) << 2)

__global__ __launch_bounds__(256, 2) void out_gemm_bf16(
    const float* __restrict__ bf, float* __restrict__ out)
{
    extern __shared__ uint32_t su[];
    const uint32_t sb = smem_u32(su);
    const int tid  = threadIdx.x, lane = tid & 31, wid = tid >> 5;
    const int wm   = (wid & 1) * 64;
    const int wn   = (wid >> 1) * 32;
    const size_t m0 = (size_t)blockIdx.y * 128;
    const int e0   = blockIdx.x * 128;
    const int lr = lane >> 2, lc = lane & 3;
    const int roff = (lane & 7) + ((lane >> 3) & 1) * 8;
    const int kwo  = (lane >> 4) * 4;
    const int frow = tid >> 2, fc = tid & 3;

    float c[4][4][4];
    #pragma unroll
    for (int i = 0; i < 4; i++)
        #pragma unroll
        for (int j = 0; j < 4; j++)
            #pragma unroll
            for (int u = 0; u < 4; u++) c[i][j][u] = 0.f;

    const char* pAh = (const char*)g_ahp;
    const char* pAl = (const char*)g_alp;
    const char* pBh = (const char*)g_wfh;
    const char* pBl = (const char*)g_wfl;

    auto issue = [&](int s) {
        const uint32_t stw = (uint32_t)(s % 3) * STG_W;
        #pragma unroll
        for (int rt = 0; rt < 2; rt++) {
            const int row = frow + rt * 64;
            const uint32_t offw = (uint32_t)row * 16u + ((uint32_t)(fc * 4) ^ SWZ(row));
            const size_t gA = (size_t)(m0 + row) * 2048 + (size_t)s * 64 + fc * 16;
            const size_t gB = (size_t)(e0 + row) * 2048 + (size_t)s * 64 + fc * 16;
            cp_async16(sb + (stw + offw) * 4,            pAh + gA);
            cp_async16(sb + (stw + PL_W + offw) * 4,     pAl + gA);
            cp_async16(sb + (stw + 2 * PL_W + offw) * 4, pBh + gB);
            cp_async16(sb + (stw + 3 * PL_W + offw) * 4, pBl + gB);
        }
        CP_COMMIT();
    };

    issue(0);
    issue(1);

    for (int t = 0; t < GKT; t++) {
        if (t < GKT - 1) { CP_WAIT(1); } else { CP_WAIT(0); }
        __syncthreads();
        if (t + 2 < GKT) issue(t + 2);

        const uint32_t stw = (uint32_t)(t % 3) * STG_W;
        #pragma unroll
        for (int ks = 0; ks < 2; ks++) {
            const int wl = ks * 8;
            uint32_t ah[4][4], al[4][4];
            #pragma unroll
            for (int mt = 0; mt < 4; mt++) {
                const int row = wm + mt * 16 + roff;
                const uint32_t ad = sb + ((stw + (uint32_t)row * 16u +
                                  ((uint32_t)(wl + kwo) ^ SWZ(row))) << 2);
                LDM_X4(ah[mt][0], ah[mt][1], ah[mt][2], ah[mt][3], ad);
                LDM_X4(al[mt][0], al[mt][1], al[mt][2], al[mt][3], ad + PL_W * 4u);
            }
            #pragma unroll
            for (int p = 0; p < 2; p++) {
                const int n = wn + p * 16 + roff;
                const uint32_t bd = sb + ((stw + 2 * PL_W + (uint32_t)n * 16u +
                                  ((uint32_t)(wl + kwo) ^ SWZ(n))) << 2);
                uint32_t h0e, h0o, h1e, h1o, l0e, l0o, l1e, l1o;
                LDM_X4(h0e, h0o, h1e, h1o, bd);
                LDM_X4(l0e, l0o, l1e, l1o, bd + PL_W * 4u);
                #pragma unroll
                for (int mt = 0; mt < 4; mt++) {
                    MMA_BF16(c[mt][2 * p],     ah[mt][0], ah[mt][1], ah[mt][2], ah[mt][3], h0e, h1e);
                    MMA_BF16(c[mt][2 * p],     al[mt][0], al[mt][1], al[mt][2], al[mt][3], h0e, h1e);
                    MMA_BF16(c[mt][2 * p],     ah[mt][0], ah[mt][1], ah[mt][2], ah[mt][3], l0e, l1e);
                    MMA_BF16(c[mt][2 * p + 1], ah[mt][0], ah[mt][1], ah[mt][2], ah[mt][3], h0o, h1o);
                    MMA_BF16(c[mt][2 * p + 1], al[mt][0], al[mt][1], al[mt][2], al[mt][3], h0o, h1o);
                    MMA_BF16(c[mt][2 * p + 1], ah[mt][0], ah[mt][1], ah[mt][2], ah[mt][3], l0o, l1o);
                }
            }
        }
        __syncthreads();
    }

    #pragma unroll
    for (int mt = 0; mt < 4; mt++) {
        #pragma unroll
        for (int nf = 0; nf < 4; nf++) {
            const int mr  = (int)m0 + wm + mt * 16 + lr;
            const int col = e0 + wn + nf * 8 + lc * 2;
            const float b0 = bf[col], b1 = bf[col + 1];
            *(float2*)&out[(size_t)mr * EMB + col] =
                make_float2(c[mt][nf][0] + b0, c[mt][nf][1] + b1);
            *(float2*)&out[(size_t)(mr + 8) * EMB + col] =
                make_float2(c[mt][nf][2] + b0, c[mt][nf][3] + b1);
        }
    }
}

// ---------------------------------------------------------------------------
extern "C" void kernel_launch(void* const* d_in, const int* in_sizes, int n_in,
                              void* d_out, int out_size)
{
    const float* vals = (const float*)d_in[0];
    const float* keys = (const float*)d_in[1];
    const float* qrs  = (const float*)d_in[2];
    const int*   mask = (const int*)d_in[3];
    const float* Wv   = (const float*)d_in[4];
    const float* Wk   = (const float*)d_in[5];
    const float* Wq   = (const float*)d_in[6];
    const float* Wf   = (const float*)d_in[7];
    const float* bf   = (const float*)d_in[8];
    float* out = (float*)d_out;

    cudaFuncSetAttribute(proj_mma,
                         cudaFuncAttributeMaxDynamicSharedMemorySize, PJ_SMEM);
    cudaFuncSetAttribute(attn_mma,
                         cudaFuncAttributeMaxDynamicSharedMemorySize, ATT_SMEM);
    cudaFuncSetAttribute(out_gemm_bf16,
                         cudaFuncAttributeMaxDynamicSharedMemorySize, SMEM_GEMM);

    w3_split<<<3, 256>>>(Wv, Wk, Wq);
    wf_split_kernel<<<EMB * EMB / 512, 256>>>(Wf);
    proj_mma<<<dim3(NB * LSEQ / 128, NH, 3), 256, PJ_SMEM>>>(vals, keys, qrs);
    attn_mma<<<dim3(NWIN * 2, NH, NB), 256, ATT_SMEM>>>(mask);
    out_gemm_bf16<<<dim3(EMB / 128, NB * LSEQ / 128), 256, SMEM_GEMM>>>(bf, out);
}